// round 2
// baseline (speedup 1.0000x reference)
#include <cuda_runtime.h>
#include <cstdint>

// Problem constants
#define B_    16
#define L_    4096
#define D_    512
#define D1_   256
#define DF_   64
#define H_    511            // (4096-16)/8 + 1
#define NROWS (B_*H_)        // 8176
#define M_    (B_*L_)        // 65536
#define EPS_  1e-8f

// Scratch (no allocations allowed)
__device__ float g_Y1[(size_t)M_*D1_];  // leaky(X@W1+b1)          : 67 MB
__device__ float g_Xe[(size_t)M_*DF_];  // encoded                  : 16.8 MB
__device__ float g_pp[NROWS*DF_];       // per-patch means          : 2 MB
__device__ float g_z [NROWS*DF_];       // per-patch aggregated     : 2 MB
__device__ float g_U [(size_t)M_*DF_];  // overlap-added            : 16.8 MB

// ---------------------------------------------------------------------------
// Register-tiled SGEMM: C[M,N] = act(A[M,K] @ B[K,N] + bias[N])
// 256 threads. BM/BN/BK tile, TM x TN microtile per thread.
// Assumes M%BM==0, N%BN==0, K%BK==0 (true for all our shapes).
// ---------------------------------------------------------------------------
template<int BM,int BN,int BK,int TM,int TN,bool ACT>
__global__ void __launch_bounds__(256)
gemm_bias(const float* __restrict__ A, const float* __restrict__ Bw,
          const float* __restrict__ bias, float* __restrict__ C,
          int M, int K, int N)
{
    __shared__ float As[BK][BM];   // transposed A tile
    __shared__ float Bs[BK][BN];

    const int tid = threadIdx.x;
    const int bx  = blockIdx.x;    // N tile
    const int by  = blockIdx.y;    // M tile

    const int tx = tid % (BN/TN);
    const int ty = tid / (BN/TN);

    float acc[TM][TN];
#pragma unroll
    for (int i=0;i<TM;i++)
#pragma unroll
        for (int j=0;j<TN;j++) acc[i][j] = 0.f;

    constexpr int A4 = BM*BK/4;
    constexpr int B4 = BK*BN/4;

    for (int k0 = 0; k0 < K; k0 += BK) {
        // load A tile (BM x BK), store transposed
#pragma unroll
        for (int idx = tid; idx < A4; idx += 256) {
            int row = idx / (BK/4);
            int c4  = idx % (BK/4);
            const float4 v = *(const float4*)&A[((size_t)(by*BM+row))*K + k0 + c4*4];
            As[c4*4+0][row] = v.x;
            As[c4*4+1][row] = v.y;
            As[c4*4+2][row] = v.z;
            As[c4*4+3][row] = v.w;
        }
        // load B tile (BK x BN)
#pragma unroll
        for (int idx = tid; idx < B4; idx += 256) {
            int row = idx / (BN/4);
            int c4  = idx % (BN/4);
            *(float4*)&Bs[row][c4*4] =
                *(const float4*)&Bw[((size_t)(k0+row))*N + bx*BN + c4*4];
        }
        __syncthreads();

#pragma unroll
        for (int kk = 0; kk < BK; kk++) {
            float a[TM], b[TN];
#pragma unroll
            for (int i=0;i<TM;i+=4) *(float4*)&a[i] = *(const float4*)&As[kk][ty*TM+i];
#pragma unroll
            for (int j=0;j<TN;j+=4) *(float4*)&b[j] = *(const float4*)&Bs[kk][tx*TN+j];
#pragma unroll
            for (int i=0;i<TM;i++)
#pragma unroll
                for (int j=0;j<TN;j++) acc[i][j] += a[i]*b[j];
        }
        __syncthreads();
    }

#pragma unroll
    for (int i=0;i<TM;i++) {
        const size_t row = (size_t)(by*BM + ty*TM + i);
#pragma unroll
        for (int j=0;j<TN;j++) {
            const int col = bx*BN + tx*TN + j;
            float v = acc[i][j] + bias[col];
            if (ACT) v = (v > 0.f) ? v : 0.01f*v;
            C[row*N + col] = v;
        }
    }
}

// ---------------------------------------------------------------------------
// Per-patch mean over PATCH=16 rows (stride 8)
// ---------------------------------------------------------------------------
__global__ void patch_mean_kernel(const float* __restrict__ Xe, float* __restrict__ pp)
{
    const int n = blockIdx.x;          // 0..NROWS-1
    const int f = threadIdx.x;         // 0..63
    const int b  = n / H_;
    const int hh = n % H_;
    const float* base = Xe + ((size_t)b*L_ + hh*8)*DF_ + f;
    float s = 0.f;
#pragma unroll
    for (int p = 0; p < 16; p++) s += base[p*DF_];
    pp[n*DF_ + f] = s * (1.f/16.f);
}

// ---------------------------------------------------------------------------
// Fused per-row attention:
//   q,k,v = pp@Wq/Wk/Wv ; qn,kn normalized
//   M[i,j] = qn_i kn_j - kn_i qn_j ; A = relu(tanh(M))
//   top-8 per row (ties -> lowest index; ties at 0 are value-irrelevant)
//   renormalize, Av_i = sum_j A_ij v_j ; z = leaky(Av@W_agg + b_agg)
// One block of 64 threads per row n.
// ---------------------------------------------------------------------------
__global__ void attn_kernel(const float* __restrict__ pp,
                            const float* __restrict__ Wq, const float* __restrict__ Wk,
                            const float* __restrict__ Wv,
                            const float* __restrict__ Wagg, const float* __restrict__ bagg,
                            float* __restrict__ z)
{
    const int n = blockIdx.x;
    const int i = threadIdx.x;   // 0..63
    __shared__ float sp[DF_], sq[DF_], sk[DF_], sv[DF_], sAv[DF_];

    sp[i] = pp[n*DF_ + i];
    __syncthreads();

    float q = 0.f, k = 0.f, v = 0.f;
#pragma unroll
    for (int j = 0; j < DF_; j++) {
        const float x = sp[j];
        q += x * Wq[j*DF_ + i];
        k += x * Wk[j*DF_ + i];
        v += x * Wv[j*DF_ + i];
    }
    sq[i] = q; sk[i] = k; sv[i] = v;
    __syncthreads();

    float nq = 0.f, nk = 0.f;
#pragma unroll
    for (int j = 0; j < DF_; j++) { nq += sq[j]*sq[j]; nk += sk[j]*sk[j]; }
    const float inv_nq = 1.f / (sqrtf(nq) + EPS_);
    const float inv_nk = 1.f / (sqrtf(nk) + EPS_);

    const float qi = sq[i]*inv_nq;
    const float ki = sk[i]*inv_nk;

    float a[DF_];
#pragma unroll
    for (int j = 0; j < DF_; j++) {
        const float m = qi*(sk[j]*inv_nk) - ki*(sq[j]*inv_nq);
        const float t = tanhf(m);
        a[j] = (t > 0.f) ? t : 0.f;
    }

    // top-8 selection, strict > gives lowest-index tie break (matches jax)
    float tmp[DF_];
#pragma unroll
    for (int j = 0; j < DF_; j++) tmp[j] = a[j];

    unsigned long long bits = 0ull;
    float sum8 = 0.f;
    for (int t = 0; t < 8; t++) {
        float best = -1.f; int bi = 0;
        for (int j = 0; j < DF_; j++)
            if (tmp[j] > best) { best = tmp[j]; bi = j; }
        tmp[bi] = -2.f;
        bits |= (1ull << bi);
        sum8 += best;
    }
    const float inv_den = 1.f / fmaxf(sum8, EPS_);

    float av = 0.f;
#pragma unroll
    for (int j = 0; j < DF_; j++)
        if ((bits >> j) & 1ull) av += a[j]*sv[j];
    av *= inv_den;

    sAv[i] = av;
    __syncthreads();

    float acc = bagg[i];
#pragma unroll
    for (int j = 0; j < DF_; j++) acc += sAv[j]*Wagg[j*DF_ + i];
    z[n*DF_ + i] = (acc > 0.f) ? acc : 0.01f*acc;
}

// ---------------------------------------------------------------------------
// Overlap-add + divide by coverage count (closed form; count is 1 or 2)
// U[b,l,f] = (1/cnt) * sum_{h covering l} z[b,h,f]
// ---------------------------------------------------------------------------
__global__ void overlap_kernel(const float* __restrict__ z, float* __restrict__ U)
{
    const int idx = blockIdx.x*blockDim.x + threadIdx.x;   // over M_*DF_
    const int f = idx % DF_;
    const int l = (idx / DF_) % L_;
    const int b = idx / (DF_*L_);

    int hlo = (l >= 15) ? (l - 15 + 7) / 8 : 0;   // ceil((l-15)/8) clamped to 0
    int hhi = l / 8; if (hhi > H_-1) hhi = H_-1;

    float s = 0.f;
    for (int hh = hlo; hh <= hhi; hh++)
        s += z[((size_t)b*H_ + hh)*DF_ + f];
    U[idx] = s / (float)(hhi - hlo + 1);
}

// ---------------------------------------------------------------------------
extern "C" void kernel_launch(void* const* d_in, const int* in_sizes, int n_in,
                              void* d_out, int out_size)
{
    const float* X    = (const float*)d_in[0];
    const float* W1   = (const float*)d_in[1];
    const float* b1   = (const float*)d_in[2];
    const float* W2   = (const float*)d_in[3];
    const float* b2   = (const float*)d_in[4];
    const float* Wq   = (const float*)d_in[5];
    const float* Wk   = (const float*)d_in[6];
    const float* Wv   = (const float*)d_in[7];
    const float* Wagg = (const float*)d_in[8];
    const float* bagg = (const float*)d_in[9];
    const float* Wdec = (const float*)d_in[10];
    const float* bdec = (const float*)d_in[11];
    float* out = (float*)d_out;

    float *Y1, *Xe, *pp, *z, *U;
    cudaGetSymbolAddress((void**)&Y1, g_Y1);
    cudaGetSymbolAddress((void**)&Xe, g_Xe);
    cudaGetSymbolAddress((void**)&pp, g_pp);
    cudaGetSymbolAddress((void**)&z,  g_z);
    cudaGetSymbolAddress((void**)&U,  g_U);

    // 1) Y1 = leaky(X @ W1 + b1)    [65536,512]x[512,256]
    gemm_bias<128,128,16,8,8,true>
        <<<dim3(D1_/128, M_/128), 256>>>(X, W1, b1, Y1, M_, D_, D1_);

    // 2) Xe = Y1 @ W2 + b2          [65536,256]x[256,64]
    gemm_bias<128,64,16,8,4,false>
        <<<dim3(1, M_/128), 256>>>(Y1, W2, b2, Xe, M_, D1_, DF_);

    // 3) per-patch means
    patch_mean_kernel<<<NROWS, 64>>>(Xe, pp);

    // 4) fused qkv + attention + top-8 + aggregate
    attn_kernel<<<NROWS, 64>>>(pp, Wq, Wk, Wv, Wagg, bagg, z);

    // 5) overlap-add with coverage normalization
    overlap_kernel<<<(M_*DF_)/256, 256>>>(z, U);

    // 6) out = U @ Wdec + bdec      [65536,64]x[64,512]
    gemm_bias<128,128,16,8,8,false>
        <<<dim3(D_/128, M_/128), 256>>>(U, Wdec, bdec, out, M_, DF_, D_);
}

// round 5
// speedup vs baseline: 1.0470x; 1.0470x over previous
#include <cuda_runtime.h>
#include <cstdint>

// Problem constants
#define B_    16
#define L_    4096
#define D_    512
#define D1_   256
#define DF_   64
#define H_    511            // (4096-16)/8 + 1
#define NROWS (B_*H_)        // 8176
#define M_    (B_*L_)        // 65536
#define EPS_  1e-8f

// Scratch (no allocations allowed)
__device__ float g_Y1[(size_t)M_*D1_];
__device__ float g_Xe[(size_t)M_*DF_];
__device__ float g_pp[NROWS*DF_];
__device__ float g_z [NROWS*DF_];
__device__ float g_U [(size_t)M_*DF_];

// ---------------------------------------------------------------------------
// f32x2 packed helpers (Blackwell FFMA2 — only reachable via PTX)
// ---------------------------------------------------------------------------
__device__ __forceinline__ unsigned long long pack2(float lo, float hi) {
    unsigned long long r;
    asm("mov.b64 %0, {%1, %2};" : "=l"(r) : "f"(lo), "f"(hi));
    return r;
}
__device__ __forceinline__ void unpack2(unsigned long long v, float& lo, float& hi) {
    asm("mov.b64 {%0, %1}, %2;" : "=f"(lo), "=f"(hi) : "l"(v));
}
__device__ __forceinline__ void ffma2(unsigned long long& d,
                                      unsigned long long a, unsigned long long b) {
    asm("fma.rn.f32x2 %0, %1, %2, %3;" : "=l"(d) : "l"(a), "l"(b), "l"(d));
}

// ---------------------------------------------------------------------------
// Register-tiled SGEMM with FFMA2: C[M,N] = act(A[M,K] @ B[K,N] + bias[N])
// 256 threads. Accumulators packed in f32x2 pairs along N.
// ---------------------------------------------------------------------------
template<int BM,int BN,int BK,int TM,int TN,bool ACT>
__global__ void __launch_bounds__(256)
gemm_bias(const float* __restrict__ A, const float* __restrict__ Bw,
          const float* __restrict__ bias, float* __restrict__ C,
          int M, int K, int N)
{
    __shared__ float As[BK][BM];   // transposed A tile
    __shared__ float Bs[BK][BN];

    const int tid = threadIdx.x;
    const int bx  = blockIdx.x;
    const int by  = blockIdx.y;

    const int tx = tid % (BN/TN);
    const int ty = tid / (BN/TN);

    constexpr int TN2 = TN/2;
    unsigned long long acc[TM][TN2];
#pragma unroll
    for (int i=0;i<TM;i++)
#pragma unroll
        for (int j=0;j<TN2;j++) acc[i][j] = 0ull;

    constexpr int A4 = BM*BK/4;
    constexpr int B4 = BK*BN/4;

    for (int k0 = 0; k0 < K; k0 += BK) {
#pragma unroll
        for (int idx = tid; idx < A4; idx += 256) {
            int row = idx / (BK/4);
            int c4  = idx % (BK/4);
            const float4 v = *(const float4*)&A[((size_t)(by*BM+row))*K + k0 + c4*4];
            As[c4*4+0][row] = v.x;
            As[c4*4+1][row] = v.y;
            As[c4*4+2][row] = v.z;
            As[c4*4+3][row] = v.w;
        }
#pragma unroll
        for (int idx = tid; idx < B4; idx += 256) {
            int row = idx / (BN/4);
            int c4  = idx % (BN/4);
            *(float4*)&Bs[row][c4*4] =
                *(const float4*)&Bw[((size_t)(k0+row))*N + bx*BN + c4*4];
        }
        __syncthreads();

#pragma unroll
        for (int kk = 0; kk < BK; kk++) {
            float a[TM];
#pragma unroll
            for (int i=0;i<TM;i+=4) *(float4*)&a[i] = *(const float4*)&As[kk][ty*TM+i];
            unsigned long long aa[TM];
#pragma unroll
            for (int i=0;i<TM;i++) aa[i] = pack2(a[i], a[i]);
            unsigned long long bb[TN2];
#pragma unroll
            for (int j=0;j<TN2;j++)
                bb[j] = *(const unsigned long long*)&Bs[kk][tx*TN + 2*j];
#pragma unroll
            for (int i=0;i<TM;i++)
#pragma unroll
                for (int j=0;j<TN2;j++) ffma2(acc[i][j], aa[i], bb[j]);
        }
        __syncthreads();
    }

#pragma unroll
    for (int i=0;i<TM;i++) {
        const size_t row = (size_t)(by*BM + ty*TM + i);
#pragma unroll
        for (int j=0;j<TN2;j++) {
            const int col = bx*BN + tx*TN + 2*j;
            float lo, hi;
            unpack2(acc[i][j], lo, hi);
            float v0 = lo + bias[col];
            float v1 = hi + bias[col+1];
            if (ACT) {
                v0 = (v0 > 0.f) ? v0 : 0.01f*v0;
                v1 = (v1 > 0.f) ? v1 : 0.01f*v1;
            }
            C[row*N + col]   = v0;
            C[row*N + col+1] = v1;
        }
    }
}

// ---------------------------------------------------------------------------
// Per-patch mean over PATCH=16 rows (stride 8)
// ---------------------------------------------------------------------------
__global__ void patch_mean_kernel(const float* __restrict__ Xe, float* __restrict__ pp)
{
    const int n = blockIdx.x;
    const int f = threadIdx.x;
    const int b  = n / H_;
    const int hh = n % H_;
    const float* base = Xe + ((size_t)b*L_ + hh*8)*DF_ + f;
    float s = 0.f;
#pragma unroll
    for (int p = 0; p < 16; p++) s += base[p*DF_];
    pp[n*DF_ + f] = s * (1.f/16.f);
}

// ---------------------------------------------------------------------------
// Fused per-row attention. Selection done on raw score s (tanh is monotone;
// relu-negative entries contribute 0 regardless of which ties are selected),
// tanh evaluated only on the 8 winners. Bitmask exclusion keeps the score
// array in registers (no local-memory spills).
// ---------------------------------------------------------------------------
__global__ void attn_kernel(const float* __restrict__ pp,
                            const float* __restrict__ Wq, const float* __restrict__ Wk,
                            const float* __restrict__ Wv,
                            const float* __restrict__ Wagg, const float* __restrict__ bagg,
                            float* __restrict__ z)
{
    const int n = blockIdx.x;
    const int i = threadIdx.x;   // 0..63
    __shared__ float sp[DF_], sq[DF_], sk[DF_], sv[DF_], sAv[DF_];

    sp[i] = pp[n*DF_ + i];
    __syncthreads();

    float q = 0.f, k = 0.f, v = 0.f;
#pragma unroll
    for (int j = 0; j < DF_; j++) {
        const float x = sp[j];
        q += x * Wq[j*DF_ + i];
        k += x * Wk[j*DF_ + i];
        v += x * Wv[j*DF_ + i];
    }
    sq[i] = q; sk[i] = k; sv[i] = v;
    __syncthreads();

    float nq = 0.f, nk = 0.f;
#pragma unroll
    for (int j = 0; j < DF_; j++) { nq += sq[j]*sq[j]; nk += sk[j]*sk[j]; }
    const float inv_nq = 1.f / (sqrtf(nq) + EPS_);
    const float inv_nk = 1.f / (sqrtf(nk) + EPS_);

    // s_ij = qn_i*kn_j - kn_i*qn_j = c1*sk[j] - c2*sq[j]
    const float c1 = (sq[i]*inv_nq) * inv_nk;
    const float c2 = (sk[i]*inv_nk) * inv_nq;

    float s[DF_];
#pragma unroll
    for (int j = 0; j < DF_; j++)
        s[j] = c1*sk[j] - c2*sq[j];

    unsigned long long bits = 0ull;
    float sum8 = 0.f, av = 0.f;
#pragma unroll
    for (int t = 0; t < 8; t++) {
        float best = -1e30f; int bi = 0;
#pragma unroll
        for (int j = 0; j < DF_; j++) {
            const bool free_j = ((bits >> j) & 1ull) == 0ull;
            if (free_j && s[j] > best) { best = s[j]; bi = j; }
        }
        bits |= (1ull << bi);
        if (best > 0.f) {
            const float a = tanhf(best);
            sum8 += a;
            av   += a * sv[bi];
        }
    }
    av *= 1.f / fmaxf(sum8, EPS_);

    sAv[i] = av;
    __syncthreads();

    float acc = bagg[i];
#pragma unroll
    for (int j = 0; j < DF_; j++) acc += sAv[j]*Wagg[j*DF_ + i];
    z[n*DF_ + i] = (acc > 0.f) ? acc : 0.01f*acc;
}

// ---------------------------------------------------------------------------
// Overlap-add + divide by coverage count (1 or 2 patches cover each l)
// ---------------------------------------------------------------------------
__global__ void overlap_kernel(const float* __restrict__ z, float* __restrict__ U)
{
    const int idx = blockIdx.x*blockDim.x + threadIdx.x;
    const int f = idx % DF_;
    const int l = (idx / DF_) % L_;
    const int b = idx / (DF_*L_);

    int hlo = (l >= 15) ? (l - 15 + 7) / 8 : 0;
    int hhi = l / 8; if (hhi > H_-1) hhi = H_-1;

    float s = 0.f;
    for (int hh = hlo; hh <= hhi; hh++)
        s += z[((size_t)b*H_ + hh)*DF_ + f];
    U[idx] = s / (float)(hhi - hlo + 1);
}

// ---------------------------------------------------------------------------
extern "C" void kernel_launch(void* const* d_in, const int* in_sizes, int n_in,
                              void* d_out, int out_size)
{
    const float* X    = (const float*)d_in[0];
    const float* W1   = (const float*)d_in[1];
    const float* b1   = (const float*)d_in[2];
    const float* W2   = (const float*)d_in[3];
    const float* b2   = (const float*)d_in[4];
    const float* Wq   = (const float*)d_in[5];
    const float* Wk   = (const float*)d_in[6];
    const float* Wv   = (const float*)d_in[7];
    const float* Wagg = (const float*)d_in[8];
    const float* bagg = (const float*)d_in[9];
    const float* Wdec = (const float*)d_in[10];
    const float* bdec = (const float*)d_in[11];
    float* out = (float*)d_out;

    float *Y1, *Xe, *pp, *z, *U;
    cudaGetSymbolAddress((void**)&Y1, g_Y1);
    cudaGetSymbolAddress((void**)&Xe, g_Xe);
    cudaGetSymbolAddress((void**)&pp, g_pp);
    cudaGetSymbolAddress((void**)&z,  g_z);
    cudaGetSymbolAddress((void**)&U,  g_U);

    // 1) Y1 = leaky(X @ W1 + b1)    [65536,512]x[512,256]
    gemm_bias<128,128,16,8,8,true>
        <<<dim3(D1_/128, M_/128), 256>>>(X, W1, b1, Y1, M_, D_, D1_);

    // 2) Xe = Y1 @ W2 + b2          [65536,256]x[256,64]
    gemm_bias<128,64,16,8,4,false>
        <<<dim3(1, M_/128), 256>>>(Y1, W2, b2, Xe, M_, D1_, DF_);

    // 3) per-patch means
    patch_mean_kernel<<<NROWS, 64>>>(Xe, pp);

    // 4) fused qkv + attention + top-8 + aggregate
    attn_kernel<<<NROWS, 64>>>(pp, Wq, Wk, Wv, Wagg, bagg, z);

    // 5) overlap-add with coverage normalization
    overlap_kernel<<<(M_*DF_)/256, 256>>>(z, U);

    // 6) out = U @ Wdec + bdec      [65536,64]x[64,512]
    gemm_bias<128,128,16,8,8,false>
        <<<dim3(D_/128, M_/128), 256>>>(U, Wdec, bdec, out, M_, DF_, D_);
}

// round 7
// speedup vs baseline: 1.2569x; 1.2006x over previous
#include <cuda_runtime.h>
#include <cstdint>

// Problem constants
#define B_    16
#define L_    4096
#define D_    512
#define D1_   256
#define DF_   64
#define H_    511            // (4096-16)/8 + 1
#define NROWS (B_*H_)        // 8176
#define M_    (B_*L_)        // 65536
#define EPS_  1e-8f

// Scratch (no allocations allowed)
__device__ float g_Y1[(size_t)M_*D1_];
__device__ float g_Xe[(size_t)M_*DF_];
__device__ float g_pp[NROWS*DF_];
__device__ float g_z [NROWS*DF_];
__device__ float g_U [(size_t)M_*DF_];

// ---------------------------------------------------------------------------
// tf32 helpers + split (error-free transformation)
// ---------------------------------------------------------------------------
__device__ __forceinline__ float tf32r(float x) {
    uint32_t o;
    asm("cvt.rna.tf32.f32 %0, %1;" : "=r"(o) : "f"(x));
    return __uint_as_float(o);
}
__device__ __forceinline__ void mma_tf32(float* d, const uint32_t* a, const uint32_t* b) {
    asm volatile(
        "mma.sync.aligned.m16n8k8.row.col.f32.tf32.tf32.f32 "
        "{%0,%1,%2,%3}, {%4,%5,%6,%7}, {%8,%9}, {%0,%1,%2,%3};"
        : "+f"(d[0]), "+f"(d[1]), "+f"(d[2]), "+f"(d[3])
        : "r"(a[0]), "r"(a[1]), "r"(a[2]), "r"(a[3]), "r"(b[0]), "r"(b[1]));
}

// ---------------------------------------------------------------------------
// Split-TF32 tensor-core GEMM: C[M,N] = act(A[M,K] @ B[K,N] + bias[N])
// BM=128, BK=16, 256 threads (8 warps as 2x4), warp tile 64 x (BN/4).
// Each operand split hi/lo; 3 MMAs (hh, lh, hl) -> ~fp32 accuracy.
// A smem stride 20: banks (20g+t4)%32 distinct across warp.
// B smem stride BN+8: as before.
// ---------------------------------------------------------------------------
template<int BN, bool ACT>
__global__ void __launch_bounds__(256)
gemm_tc(const float* __restrict__ A, const float* __restrict__ Bw,
        const float* __restrict__ bias, float* __restrict__ C,
        int M, int K, int N)
{
    constexpr int BM = 128, BK = 16;
    constexpr int WN = BN/4;        // warp n extent
    constexpr int NT = WN/8;        // n tiles per warp
    constexpr int MT = 4;           // m tiles per warp (64/16)
    constexpr int AS = 20;          // A smem row stride (floats)
    constexpr int BS = BN + 8;      // B smem row stride (floats)
    constexpr int ALD = (BM*BK)/1024;         // A float4 loads per thread (=2)
    constexpr int BLD = (BK*BN)/1024;         // B float4 loads per thread

    __shared__ float As_hi[BM*AS], As_lo[BM*AS];
    __shared__ float Bs_hi[BK*BS], Bs_lo[BK*BS];

    const int tid  = threadIdx.x;
    const int warp = tid >> 5, lane = tid & 31;
    const int wm = warp >> 2, wn = warp & 3;
    const int g  = lane >> 2, t4 = lane & 3;

    float acc[MT][NT][4];
#pragma unroll
    for (int mt=0; mt<MT; mt++)
#pragma unroll
        for (int nt=0; nt<NT; nt++)
#pragma unroll
            for (int c=0; c<4; c++) acc[mt][nt][c] = 0.f;

    const float* Ab = A + (size_t)blockIdx.y*BM*K;
    const float* Bb = Bw + blockIdx.x*BN;

    int arow[ALD], acol[ALD];
#pragma unroll
    for (int i=0;i<ALD;i++) { int idx = tid + i*256; arow[i] = idx >> 2; acol[i] = (idx & 3)*4; }
    int brow[BLD], bcol[BLD];
#pragma unroll
    for (int i=0;i<BLD;i++) { int idx = tid + i*256; brow[i] = idx/(BN/4); bcol[i] = (idx%(BN/4))*4; }

    float4 ra[ALD], rb[BLD];

    auto gload = [&](int k0) {
#pragma unroll
        for (int i=0;i<ALD;i++)
            ra[i] = *(const float4*)&Ab[(size_t)arow[i]*K + k0 + acol[i]];
#pragma unroll
        for (int i=0;i<BLD;i++)
            rb[i] = *(const float4*)&Bb[(size_t)(k0 + brow[i])*N + bcol[i]];
    };
    auto sstore = [&]() {
#pragma unroll
        for (int i=0;i<ALD;i++) {
            const float* v = (const float*)&ra[i];
#pragma unroll
            for (int c=0;c<4;c++) {
                const float hi = tf32r(v[c]);
                As_hi[arow[i]*AS + acol[i] + c] = hi;
                As_lo[arow[i]*AS + acol[i] + c] = tf32r(v[c] - hi);
            }
        }
#pragma unroll
        for (int i=0;i<BLD;i++) {
            const float* v = (const float*)&rb[i];
#pragma unroll
            for (int c=0;c<4;c++) {
                const float hi = tf32r(v[c]);
                Bs_hi[brow[i]*BS + bcol[i] + c] = hi;
                Bs_lo[brow[i]*BS + bcol[i] + c] = tf32r(v[c] - hi);
            }
        }
    };

    gload(0);
    sstore();
    __syncthreads();

    for (int k0 = 0; k0 < K; k0 += BK) {
        const bool has_next = (k0 + BK) < K;
        if (has_next) gload(k0 + BK);

#pragma unroll
        for (int kk = 0; kk < 2; kk++) {
            const int k = kk*8;
            uint32_t ah[MT][4], al[MT][4];
#pragma unroll
            for (int mt=0; mt<MT; mt++) {
                const int r0 = wm*64 + mt*16 + g;
                ah[mt][0] = __float_as_uint(As_hi[r0*AS + k + t4]);
                ah[mt][1] = __float_as_uint(As_hi[(r0+8)*AS + k + t4]);
                ah[mt][2] = __float_as_uint(As_hi[r0*AS + k + t4 + 4]);
                ah[mt][3] = __float_as_uint(As_hi[(r0+8)*AS + k + t4 + 4]);
                al[mt][0] = __float_as_uint(As_lo[r0*AS + k + t4]);
                al[mt][1] = __float_as_uint(As_lo[(r0+8)*AS + k + t4]);
                al[mt][2] = __float_as_uint(As_lo[r0*AS + k + t4 + 4]);
                al[mt][3] = __float_as_uint(As_lo[(r0+8)*AS + k + t4 + 4]);
            }
            uint32_t bh[NT][2], bl[NT][2];
#pragma unroll
            for (int nt=0; nt<NT; nt++) {
                const int c = wn*WN + nt*8 + g;
                bh[nt][0] = __float_as_uint(Bs_hi[(k+t4)*BS + c]);
                bh[nt][1] = __float_as_uint(Bs_hi[(k+t4+4)*BS + c]);
                bl[nt][0] = __float_as_uint(Bs_lo[(k+t4)*BS + c]);
                bl[nt][1] = __float_as_uint(Bs_lo[(k+t4+4)*BS + c]);
            }
#pragma unroll
            for (int mt=0; mt<MT; mt++)
#pragma unroll
                for (int nt=0; nt<NT; nt++) {
                    mma_tf32(acc[mt][nt], al[mt], bh[nt]);   // lo*hi
                    mma_tf32(acc[mt][nt], ah[mt], bl[nt]);   // hi*lo
                    mma_tf32(acc[mt][nt], ah[mt], bh[nt]);   // hi*hi
                }
        }

        if (has_next) {
            __syncthreads();
            sstore();
            __syncthreads();
        }
    }

    // Epilogue: bias + optional leaky relu, float2 stores
#pragma unroll
    for (int mt=0; mt<MT; mt++) {
        const size_t r0 = (size_t)blockIdx.y*BM + wm*64 + mt*16 + g;
        const size_t r1 = r0 + 8;
#pragma unroll
        for (int nt=0; nt<NT; nt++) {
            const int c = blockIdx.x*BN + wn*WN + nt*8 + t4*2;
            const float b0 = bias[c], b1 = bias[c+1];
            float v00 = acc[mt][nt][0] + b0;
            float v01 = acc[mt][nt][1] + b1;
            float v10 = acc[mt][nt][2] + b0;
            float v11 = acc[mt][nt][3] + b1;
            if (ACT) {
                v00 = (v00 > 0.f) ? v00 : 0.01f*v00;
                v01 = (v01 > 0.f) ? v01 : 0.01f*v01;
                v10 = (v10 > 0.f) ? v10 : 0.01f*v10;
                v11 = (v11 > 0.f) ? v11 : 0.01f*v11;
            }
            float2 s0; s0.x = v00; s0.y = v01;
            float2 s1; s1.x = v10; s1.y = v11;
            *(float2*)&C[r0*N + c] = s0;
            *(float2*)&C[r1*N + c] = s1;
        }
    }
}

// ---------------------------------------------------------------------------
// Per-patch mean over PATCH=16 rows (stride 8)
// ---------------------------------------------------------------------------
__global__ void patch_mean_kernel(const float* __restrict__ Xe, float* __restrict__ pp)
{
    const int n = blockIdx.x;
    const int f = threadIdx.x;
    const int b  = n / H_;
    const int hh = n % H_;
    const float* base = Xe + ((size_t)b*L_ + hh*8)*DF_ + f;
    float s = 0.f;
#pragma unroll
    for (int p = 0; p < 16; p++) s += base[p*DF_];
    pp[n*DF_ + f] = s * (1.f/16.f);
}

// ---------------------------------------------------------------------------
// Fused per-row attention, 4 rows per 256-thread block.
// Scores computed on the fly; top-8 kept in a sorted 8-entry register heap.
// Strict-> insertion reproduces jax's lowest-index tie break; sub-top-8 /
// negative ties are value-irrelevant. tanh on <=8 positive winners only.
// ---------------------------------------------------------------------------
__global__ void __launch_bounds__(256)
attn_kernel(const float* __restrict__ pp,
            const float* __restrict__ Wq, const float* __restrict__ Wk,
            const float* __restrict__ Wv,
            const float* __restrict__ Wagg, const float* __restrict__ bagg,
            float* __restrict__ z)
{
    const int r = threadIdx.x >> 6;      // row within block (0..3)
    const int i = threadIdx.x & 63;      // feature index
    const int n = blockIdx.x*4 + r;

    __shared__ float sp[4][DF_], sq[4][DF_], sk[4][DF_], sv[4][DF_], sAv[4][DF_];

    sp[r][i] = pp[n*DF_ + i];
    __syncthreads();

    float q = 0.f, k = 0.f, v = 0.f;
#pragma unroll
    for (int j = 0; j < DF_; j++) {
        const float x = sp[r][j];
        q += x * Wq[j*DF_ + i];
        k += x * Wk[j*DF_ + i];
        v += x * Wv[j*DF_ + i];
    }
    sq[r][i] = q; sk[r][i] = k; sv[r][i] = v;
    __syncthreads();

    float nq = 0.f, nk = 0.f;
#pragma unroll
    for (int j = 0; j < DF_; j++) { nq += sq[r][j]*sq[r][j]; nk += sk[r][j]*sk[r][j]; }
    const float inv_nq = 1.f / (sqrtf(nq) + EPS_);
    const float inv_nk = 1.f / (sqrtf(nk) + EPS_);

    // s_ij = c1*sk[j] - c2*sq[j]
    const float c1 = (sq[r][i]*inv_nq) * inv_nk;
    const float c2 = (sk[r][i]*inv_nk) * inv_nq;

    float hv[8]; int hi8[8];
#pragma unroll
    for (int t = 0; t < 8; t++) { hv[t] = -1e30f; hi8[t] = 0; }

    for (int j = 0; j < DF_; j++) {
        const float x = c1*sk[r][j] - c2*sq[r][j];
        if (x > hv[0]) {
            hv[0] = x; hi8[0] = j;
#pragma unroll
            for (int t = 0; t < 7; t++) {
                if (hv[t] > hv[t+1]) {
                    const float tv = hv[t]; hv[t] = hv[t+1]; hv[t+1] = tv;
                    const int   ti = hi8[t]; hi8[t] = hi8[t+1]; hi8[t+1] = ti;
                }
            }
        }
    }

    float sum8 = 0.f, av = 0.f;
#pragma unroll
    for (int t = 0; t < 8; t++) {
        if (hv[t] > 0.f) {
            const float a = tanhf(hv[t]);
            sum8 += a;
            av   += a * sv[r][hi8[t]];
        }
    }
    av *= 1.f / fmaxf(sum8, EPS_);

    sAv[r][i] = av;
    __syncthreads();

    float acc = bagg[i];
#pragma unroll
    for (int j = 0; j < DF_; j++) acc += sAv[r][j]*Wagg[j*DF_ + i];
    z[n*DF_ + i] = (acc > 0.f) ? acc : 0.01f*acc;
}

// ---------------------------------------------------------------------------
// Overlap-add + divide by coverage count (1 or 2 patches cover each l)
// ---------------------------------------------------------------------------
__global__ void overlap_kernel(const float* __restrict__ z, float* __restrict__ U)
{
    const int idx = blockIdx.x*blockDim.x + threadIdx.x;
    const int f = idx % DF_;
    const int l = (idx / DF_) % L_;
    const int b = idx / (DF_*L_);

    int hlo = (l >= 15) ? (l - 15 + 7) / 8 : 0;
    int hhi = l / 8; if (hhi > H_-1) hhi = H_-1;

    float s = 0.f;
    for (int hh = hlo; hh <= hhi; hh++)
        s += z[((size_t)b*H_ + hh)*DF_ + f];
    U[idx] = s / (float)(hhi - hlo + 1);
}

// ---------------------------------------------------------------------------
extern "C" void kernel_launch(void* const* d_in, const int* in_sizes, int n_in,
                              void* d_out, int out_size)
{
    const float* X    = (const float*)d_in[0];
    const float* W1   = (const float*)d_in[1];
    const float* b1   = (const float*)d_in[2];
    const float* W2   = (const float*)d_in[3];
    const float* b2   = (const float*)d_in[4];
    const float* Wq   = (const float*)d_in[5];
    const float* Wk   = (const float*)d_in[6];
    const float* Wv   = (const float*)d_in[7];
    const float* Wagg = (const float*)d_in[8];
    const float* bagg = (const float*)d_in[9];
    const float* Wdec = (const float*)d_in[10];
    const float* bdec = (const float*)d_in[11];
    float* out = (float*)d_out;

    float *Y1, *Xe, *pp, *z, *U;
    cudaGetSymbolAddress((void**)&Y1, g_Y1);
    cudaGetSymbolAddress((void**)&Xe, g_Xe);
    cudaGetSymbolAddress((void**)&pp, g_pp);
    cudaGetSymbolAddress((void**)&z,  g_z);
    cudaGetSymbolAddress((void**)&U,  g_U);

    // 1) Y1 = leaky(X @ W1 + b1)    [65536,512]x[512,256]
    gemm_tc<128,true>
        <<<dim3(D1_/128, M_/128), 256>>>(X, W1, b1, Y1, M_, D_, D1_);

    // 2) Xe = Y1 @ W2 + b2          [65536,256]x[256,64]
    gemm_tc<64,false>
        <<<dim3(1, M_/128), 256>>>(Y1, W2, b2, Xe, M_, D1_, DF_);

    // 3) per-patch means
    patch_mean_kernel<<<NROWS, 64>>>(Xe, pp);

    // 4) fused qkv + attention + top-8 + aggregate (4 rows / block)
    attn_kernel<<<NROWS/4, 256>>>(pp, Wq, Wk, Wv, Wagg, bagg, z);

    // 5) overlap-add with coverage normalization
    overlap_kernel<<<(M_*DF_)/256, 256>>>(z, U);

    // 6) out = U @ Wdec + bdec      [65536,64]x[64,512]
    gemm_tc<128,false>
        <<<dim3(D_/128, M_/128), 256>>>(U, Wdec, bdec, out, M_, DF_, D_);
}

// round 9
// speedup vs baseline: 1.7649x; 1.4041x over previous
#include <cuda_runtime.h>
#include <cuda_fp16.h>
#include <cstdint>

// Problem constants
#define B_    16
#define L_    4096
#define D_    512
#define D1_   256
#define DF_   64
#define H_    511            // (4096-16)/8 + 1
#define NROWS (B_*H_)        // 8176
#define M_    (B_*L_)        // 65536
#define EPS_  1e-8f

// Scratch (no allocations allowed)
__device__ float g_Y1[(size_t)M_*D1_];       // leaky(X@W1+b1)     : 67 MB
__device__ float g_pp[NROWS*DF_];            // per-patch encodings: 2 MB
__device__ float g_z [NROWS*DF_];            // aggregated          : 2 MB
__device__ float g_zd[(size_t)NROWS*D_];     // z @ Wdec            : 16.7 MB

// ---------------------------------------------------------------------------
// fp16 split helpers
// ---------------------------------------------------------------------------
__device__ __forceinline__ uint32_t f2h2(float a, float b) {
    __half2 h = __floats2half2_rn(a, b);
    return *reinterpret_cast<uint32_t*>(&h);
}
__device__ __forceinline__ void mma_f16(float* d, const uint32_t* a, const uint32_t* b) {
    asm volatile(
        "mma.sync.aligned.m16n8k16.row.col.f32.f16.f16.f32 "
        "{%0,%1,%2,%3}, {%4,%5,%6,%7}, {%8,%9}, {%0,%1,%2,%3};"
        : "+f"(d[0]), "+f"(d[1]), "+f"(d[2]), "+f"(d[3])
        : "r"(a[0]), "r"(a[1]), "r"(a[2]), "r"(a[3]), "r"(b[0]), "r"(b[1]));
}

// ---------------------------------------------------------------------------
// Split-FP16 tensor-core GEMM: C[M,N] = leaky(A[M,K] @ B[K,N] + bias[N])
// BM=BN=128, BK=32. 256 threads (8 warps, 2x4). Warp tile 64x32.
// Each f32 operand split v = hi + lo (fp16 each, 22 combined mantissa bits);
// 3 MMA products (hh, hl, lh) -> near-fp32 accuracy, fp32 accumulate.
// SMEM half2 arrays, row stride 20 (16 + pad 4): conflict-free frag loads.
// Register-staged global->smem double buffering (R7-validated pattern).
// ---------------------------------------------------------------------------
__global__ void __launch_bounds__(256)
gemm_h(const float* __restrict__ A, const float* __restrict__ Bw,
       const float* __restrict__ bias, float* __restrict__ C,
       int M, int K, int N)
{
    constexpr int ST = 20;          // smem row stride in half2 units
    __shared__ uint32_t As_h[128*ST], As_l[128*ST];
    __shared__ uint32_t Bs_h[128*ST], Bs_l[128*ST];

    const int tid  = threadIdx.x;
    const int warp = tid >> 5, lane = tid & 31;
    const int wm = warp >> 2, wn = warp & 3;
    const int g  = lane >> 2, t4 = lane & 3;

    float acc[4][4][4];
#pragma unroll
    for (int mt=0; mt<4; mt++)
#pragma unroll
        for (int nt=0; nt<4; nt++)
#pragma unroll
            for (int c=0; c<4; c++) acc[mt][nt][c] = 0.f;

    const float* Ab = A + (size_t)blockIdx.y*128*K;
    const float* Bb = Bw + blockIdx.x*128;

    int arow[4], acol[4];
#pragma unroll
    for (int i=0;i<4;i++) { int idx = tid + i*256; arow[i] = idx >> 3; acol[i] = (idx & 7)*4; }
    int bn[8], bkp[8];
#pragma unroll
    for (int i=0;i<8;i++) { int idx = tid + i*256; bn[i] = idx & 127; bkp[i] = idx >> 7; }

    float4 ra[4];
    float  rb0[8], rb1[8];

    auto gload = [&](int k0) {
#pragma unroll
        for (int i=0;i<4;i++)
            ra[i] = *(const float4*)&Ab[(size_t)arow[i]*K + k0 + acol[i]];
#pragma unroll
        for (int i=0;i<8;i++) {
            rb0[i] = Bb[(size_t)(k0 + 2*bkp[i] + 0)*N + bn[i]];
            rb1[i] = Bb[(size_t)(k0 + 2*bkp[i] + 1)*N + bn[i]];
        }
    };
    auto sstore = [&]() {
#pragma unroll
        for (int i=0;i<4;i++) {
            const float* v = (const float*)&ra[i];
            float h[4], l[4];
#pragma unroll
            for (int c=0;c<4;c++) {
                h[c] = __half2float(__float2half_rn(v[c]));
                l[c] = v[c] - h[c];
            }
            const int base = arow[i]*ST + (acol[i] >> 1);
            As_h[base+0] = f2h2(h[0], h[1]);
            As_h[base+1] = f2h2(h[2], h[3]);
            As_l[base+0] = f2h2(l[0], l[1]);
            As_l[base+1] = f2h2(l[2], l[3]);
        }
#pragma unroll
        for (int i=0;i<8;i++) {
            const float h0 = __half2float(__float2half_rn(rb0[i]));
            const float h1 = __half2float(__float2half_rn(rb1[i]));
            const int base = bn[i]*ST + bkp[i];
            Bs_h[base] = f2h2(h0, h1);
            Bs_l[base] = f2h2(rb0[i] - h0, rb1[i] - h1);
        }
    };

    gload(0);
    sstore();
    __syncthreads();

    for (int k0 = 0; k0 < K; k0 += 32) {
        const bool has_next = (k0 + 32) < K;
        if (has_next) gload(k0 + 32);

#pragma unroll
        for (int s = 0; s < 2; s++) {
            const int s8 = s*8;
            uint32_t ah[4][4], al[4][4];
#pragma unroll
            for (int mt=0; mt<4; mt++) {
                const int r0 = wm*64 + mt*16 + g;
                const int b0 = r0*ST + s8 + t4, b1 = (r0+8)*ST + s8 + t4;
                ah[mt][0] = As_h[b0];   ah[mt][1] = As_h[b1];
                ah[mt][2] = As_h[b0+4]; ah[mt][3] = As_h[b1+4];
                al[mt][0] = As_l[b0];   al[mt][1] = As_l[b1];
                al[mt][2] = As_l[b0+4]; al[mt][3] = As_l[b1+4];
            }
            uint32_t bh[4][2], bl[4][2];
#pragma unroll
            for (int nt=0; nt<4; nt++) {
                const int c = wn*32 + nt*8 + g;
                const int bb = c*ST + s8 + t4;
                bh[nt][0] = Bs_h[bb]; bh[nt][1] = Bs_h[bb+4];
                bl[nt][0] = Bs_l[bb]; bl[nt][1] = Bs_l[bb+4];
            }
#pragma unroll
            for (int mt=0; mt<4; mt++)
#pragma unroll
                for (int nt=0; nt<4; nt++) {
                    mma_f16(acc[mt][nt], al[mt], bh[nt]);   // lo*hi
                    mma_f16(acc[mt][nt], ah[mt], bl[nt]);   // hi*lo
                    mma_f16(acc[mt][nt], ah[mt], bh[nt]);   // hi*hi
                }
        }

        if (has_next) {
            __syncthreads();
            sstore();
            __syncthreads();
        }
    }

    // Epilogue: bias + leaky relu, float2 stores
#pragma unroll
    for (int mt=0; mt<4; mt++) {
        const size_t r0 = (size_t)blockIdx.y*128 + wm*64 + mt*16 + g;
        const size_t r1 = r0 + 8;
#pragma unroll
        for (int nt=0; nt<4; nt++) {
            const int c = blockIdx.x*128 + wn*32 + nt*8 + t4*2;
            const float b0 = bias[c], b1 = bias[c+1];
            float v00 = acc[mt][nt][0] + b0;
            float v01 = acc[mt][nt][1] + b1;
            float v10 = acc[mt][nt][2] + b0;
            float v11 = acc[mt][nt][3] + b1;
            v00 = (v00 > 0.f) ? v00 : 0.01f*v00;
            v01 = (v01 > 0.f) ? v01 : 0.01f*v01;
            v10 = (v10 > 0.f) ? v10 : 0.01f*v10;
            v11 = (v11 > 0.f) ? v11 : 0.01f*v11;
            float2 s0; s0.x = v00; s0.y = v01;
            float2 s1; s1.x = v10; s1.y = v11;
            *(float2*)&C[r0*N + c] = s0;
            *(float2*)&C[r1*N + c] = s1;
        }
    }
}

// ---------------------------------------------------------------------------
// Fused patch-mean (over Y1, 16 rows stride 8) + small GEMM with W2:
//   pp[n] = (mean_p Y1[rows(n)]) @ W2 + b2       (linearity of the mean)
// Block handles 8 patch rows; W2 read once per block (1022 x 64KB from L2).
// ---------------------------------------------------------------------------
__global__ void __launch_bounds__(256)
pool_pp_kernel(const float* __restrict__ Y1, const float* __restrict__ W2,
               const float* __restrict__ b2, float* __restrict__ pp)
{
    __shared__ float sP[8][D1_];
    const int tid = threadIdx.x;

#pragma unroll
    for (int rr = 0; rr < 8; rr++) {
        const int n = blockIdx.x*8 + rr;
        const int b = n / H_, h = n % H_;
        const float* base = Y1 + ((size_t)b*L_ + h*8)*D1_ + tid;
        float s = 0.f;
#pragma unroll
        for (int p = 0; p < 16; p++) s += base[p*D1_];
        sP[rr][tid] = s * (1.f/16.f);
    }
    __syncthreads();

    const int i = tid & 63;
#pragma unroll
    for (int rr = tid >> 6; rr < 8; rr += 4) {
        float acc = b2[i];
#pragma unroll
        for (int j = 0; j < D1_; j++) acc += sP[rr][j] * W2[j*DF_ + i];
        pp[(blockIdx.x*8 + rr)*DF_ + i] = acc;
    }
}

// ---------------------------------------------------------------------------
// Fused per-row attention, 4 rows per 256-thread block.
// Branchless top-8 on raw scores (tanh monotone; zero/negative ties are
// value-irrelevant): orderable u32 keys with inverted index in low 6 bits,
// sorted 8-reg heap via unconditional compare-swaps. Winners' scores
// recomputed exactly; tanh on positives only.
// ---------------------------------------------------------------------------
__global__ void __launch_bounds__(256)
attn_kernel(const float* __restrict__ pp,
            const float* __restrict__ Wq, const float* __restrict__ Wk,
            const float* __restrict__ Wv,
            const float* __restrict__ Wagg, const float* __restrict__ bagg,
            float* __restrict__ z)
{
    const int r = threadIdx.x >> 6;      // row within block (0..3)
    const int i = threadIdx.x & 63;      // feature index
    const int n = blockIdx.x*4 + r;

    __shared__ float sp[4][DF_], sq[4][DF_], sk[4][DF_], sv[4][DF_], sAv[4][DF_];

    sp[r][i] = pp[n*DF_ + i];
    __syncthreads();

    float q = 0.f, k = 0.f, v = 0.f;
#pragma unroll
    for (int j = 0; j < DF_; j++) {
        const float x = sp[r][j];
        q += x * Wq[j*DF_ + i];
        k += x * Wk[j*DF_ + i];
        v += x * Wv[j*DF_ + i];
    }
    sq[r][i] = q; sk[r][i] = k; sv[r][i] = v;
    __syncthreads();

    float nq = 0.f, nk = 0.f;
#pragma unroll
    for (int j = 0; j < DF_; j++) { nq += sq[r][j]*sq[r][j]; nk += sk[r][j]*sk[r][j]; }
    const float inv_nq = 1.f / (sqrtf(nq) + EPS_);
    const float inv_nk = 1.f / (sqrtf(nk) + EPS_);

    const float c1 = (sq[r][i]*inv_nq) * inv_nk;
    const float c2 = (sk[r][i]*inv_nk) * inv_nq;

    uint32_t h[8];
#pragma unroll
    for (int t = 0; t < 8; t++) h[t] = 0u;

#pragma unroll
    for (int j = 0; j < DF_; j++) {
        const float s = c1*sk[r][j] - c2*sq[r][j];
        uint32_t u = __float_as_uint(s);
        u = ((int32_t)u < 0) ? ~u : (u | 0x80000000u);
        u = (u & 0xFFFFFFC0u) | (uint32_t)(63 - j);
        h[0] = (h[0] > u) ? h[0] : u;      // replace current min if larger
#pragma unroll
        for (int t = 0; t < 7; t++) {      // single bubble pass re-sorts
            const uint32_t lo = (h[t] < h[t+1]) ? h[t] : h[t+1];
            const uint32_t hi = (h[t] < h[t+1]) ? h[t+1] : h[t];
            h[t] = lo; h[t+1] = hi;
        }
    }

    float sum8 = 0.f, av = 0.f;
#pragma unroll
    for (int t = 0; t < 8; t++) {
        const int j = 63 - (int)(h[t] & 63u);
        const float s = c1*sk[r][j] - c2*sq[r][j];
        if (s > 0.f) {
            const float e = __expf(2.f*s);
            const float a = 1.f - __fdividef(2.f, e + 1.f);   // tanh(s)
            sum8 += a;
            av   += a * sv[r][j];
        }
    }
    av *= 1.f / fmaxf(sum8, EPS_);

    sAv[r][i] = av;
    __syncthreads();

    float acc = bagg[i];
#pragma unroll
    for (int j = 0; j < DF_; j++) acc += sAv[r][j]*Wagg[j*DF_ + i];
    z[n*DF_ + i] = (acc > 0.f) ? acc : 0.01f*acc;
}

// ---------------------------------------------------------------------------
// zd = z @ Wdec  (8176 x 64 x 512, FFMA; Wdec staged in smem per 16-row block)
// ---------------------------------------------------------------------------
__global__ void __launch_bounds__(256)
zdec_kernel(const float* __restrict__ z, const float* __restrict__ Wdec,
            float* __restrict__ zd)
{
    __shared__ float zs[16*DF_];
    __shared__ float ws[DF_*132];
    const int tid = threadIdx.x;
    const int n0 = blockIdx.x*16;

    {
        const int r = tid >> 4, c4 = (tid & 15)*4;
        *(float4*)&zs[r*DF_ + c4] = *(const float4*)&z[(size_t)(n0+r)*DF_ + c4];
    }

    const int ct64 = tid & 63;
    const int rt   = tid >> 6;

    for (int ct = 0; ct < 4; ct++) {
        __syncthreads();
#pragma unroll
        for (int i = 0; i < 8; i++) {
            const int idx = tid + i*256;            // 0..2047 float4
            const int r = idx >> 5, c4 = (idx & 31)*4;
            *(float4*)&ws[r*132 + c4] = *(const float4*)&Wdec[(size_t)r*D_ + ct*128 + c4];
        }
        __syncthreads();

        float acc[4][2];
#pragma unroll
        for (int r=0;r<4;r++) { acc[r][0]=0.f; acc[r][1]=0.f; }
#pragma unroll
        for (int k = 0; k < DF_; k++) {
            const float2 w = *(const float2*)&ws[k*132 + ct64*2];
#pragma unroll
            for (int r = 0; r < 4; r++) {
                const float zv = zs[(rt*4+r)*DF_ + k];
                acc[r][0] += zv*w.x;
                acc[r][1] += zv*w.y;
            }
        }
#pragma unroll
        for (int r = 0; r < 4; r++) {
            float2 o; o.x = acc[r][0]; o.y = acc[r][1];
            *(float2*)&zd[(size_t)(n0 + rt*4 + r)*D_ + ct*128 + ct64*2] = o;
        }
    }
}

// ---------------------------------------------------------------------------
// Final overlap-add in decoder space: out = overlap(zd)/cnt + bdec
// (linearity: overlap(z)/cnt @ Wdec == overlap(z @ Wdec)/cnt)
// ---------------------------------------------------------------------------
__global__ void overlap2_kernel(const float* __restrict__ zd,
                                const float* __restrict__ bdec,
                                float* __restrict__ out)
{
    const int idx = blockIdx.x*blockDim.x + threadIdx.x;   // over M_*D_
    const int c = idx & 511;
    const int l = (idx >> 9) & 4095;
    const int b = idx >> 21;

    int hlo = (l >= 15) ? (l - 8) / 8 : 0;
    int hhi = l / 8; if (hhi > H_-1) hhi = H_-1;

    float s = 0.f;
    for (int hh = hlo; hh <= hhi; hh++)
        s += zd[((size_t)b*H_ + hh)*D_ + c];
    out[idx] = s / (float)(hhi - hlo + 1) + bdec[c];
}

// ---------------------------------------------------------------------------
extern "C" void kernel_launch(void* const* d_in, const int* in_sizes, int n_in,
                              void* d_out, int out_size)
{
    const float* X    = (const float*)d_in[0];
    const float* W1   = (const float*)d_in[1];
    const float* b1   = (const float*)d_in[2];
    const float* W2   = (const float*)d_in[3];
    const float* b2   = (const float*)d_in[4];
    const float* Wq   = (const float*)d_in[5];
    const float* Wk   = (const float*)d_in[6];
    const float* Wv   = (const float*)d_in[7];
    const float* Wagg = (const float*)d_in[8];
    const float* bagg = (const float*)d_in[9];
    const float* Wdec = (const float*)d_in[10];
    const float* bdec = (const float*)d_in[11];
    float* out = (float*)d_out;

    float *Y1, *pp, *z, *zd;
    cudaGetSymbolAddress((void**)&Y1, g_Y1);
    cudaGetSymbolAddress((void**)&pp, g_pp);
    cudaGetSymbolAddress((void**)&z,  g_z);
    cudaGetSymbolAddress((void**)&zd, g_zd);

    // 1) Y1 = leaky(X @ W1 + b1)    [65536,512]x[512,256]  (fp16-split MMA)
    gemm_h<<<dim3(D1_/128, M_/128), 256>>>(X, W1, b1, Y1, M_, D_, D1_);

    // 2) pp = patchmean(Y1) @ W2 + b2   [8176,256]x[256,64]
    pool_pp_kernel<<<NROWS/8, 256>>>(Y1, W2, b2, pp);

    // 3) fused qkv + attention + top-8 + aggregate (4 rows / block)
    attn_kernel<<<NROWS/4, 256>>>(pp, Wq, Wk, Wv, Wagg, bagg, z);

    // 4) zd = z @ Wdec              [8176,64]x[64,512]
    zdec_kernel<<<NROWS/16, 256>>>(z, Wdec, zd);

    // 5) out = overlap(zd)/cnt + bdec
    overlap2_kernel<<<(M_*D_)/256, 256>>>(zd, bdec, out);
}

// round 10
// speedup vs baseline: 1.7900x; 1.0143x over previous
#include <cuda_runtime.h>
#include <cuda_fp16.h>
#include <cstdint>

// Problem constants
#define B_    16
#define L_    4096
#define D_    512
#define D1_   256
#define DF_   64
#define H_    511            // (4096-16)/8 + 1
#define NROWS (B_*H_)        // 8176
#define M_    (B_*L_)        // 65536
#define NOCT  (M_/8)         // 8192 octet rows (512 per batch)
#define EPS_  1e-8f

// Scratch (no allocations allowed)
__device__ float g_S [(size_t)NOCT*D1_];     // octet sums of leaky(X@W1+b1): 8.4 MB
__device__ float g_pp[NROWS*DF_];            // per-patch encodings
__device__ float g_z [NROWS*DF_];            // aggregated
__device__ float g_zd[(size_t)NROWS*D_];     // z @ Wdec

// ---------------------------------------------------------------------------
// fp16 split helpers
// ---------------------------------------------------------------------------
__device__ __forceinline__ uint32_t f2h2(float a, float b) {
    __half2 h = __floats2half2_rn(a, b);
    return *reinterpret_cast<uint32_t*>(&h);
}
__device__ __forceinline__ void mma_f16(float* d, const uint32_t* a, const uint32_t* b) {
    asm volatile(
        "mma.sync.aligned.m16n8k16.row.col.f32.f16.f16.f32 "
        "{%0,%1,%2,%3}, {%4,%5,%6,%7}, {%8,%9}, {%0,%1,%2,%3};"
        : "+f"(d[0]), "+f"(d[1]), "+f"(d[2]), "+f"(d[3])
        : "r"(a[0]), "r"(a[1]), "r"(a[2]), "r"(a[3]), "r"(b[0]), "r"(b[1]));
}

// ---------------------------------------------------------------------------
// Split-FP16 tensor-core GEMM1 with fused octet-sum epilogue:
//   S[oct, col] = sum_{8 rows of oct} leaky(X@W1 + b1)
// BM=BN=128, BK=32. 256 threads (8 warps, 2x4). Warp tile 64x32.
// v = hi + lo fp16 split; 3 MMA products (hh, hl, lh), fp32 accumulate.
// Octet sum: rows of one octet sit at lane stride 4 in the fragment ->
// 3 bfly shuffles; lanes t4<4 store. Output is 8x smaller than Y1.
// ---------------------------------------------------------------------------
__global__ void __launch_bounds__(256)
gemm_h(const float* __restrict__ A, const float* __restrict__ Bw,
       const float* __restrict__ bias, float* __restrict__ S,
       int M, int K, int N)
{
    constexpr int ST = 20;          // smem row stride in half2 units
    __shared__ uint32_t As_h[128*ST], As_l[128*ST];
    __shared__ uint32_t Bs_h[128*ST], Bs_l[128*ST];

    const int tid  = threadIdx.x;
    const int warp = tid >> 5, lane = tid & 31;
    const int wm = warp >> 2, wn = warp & 3;
    const int g  = lane >> 2, t4 = lane & 3;

    float acc[4][4][4];
#pragma unroll
    for (int mt=0; mt<4; mt++)
#pragma unroll
        for (int nt=0; nt<4; nt++)
#pragma unroll
            for (int c=0; c<4; c++) acc[mt][nt][c] = 0.f;

    const float* Ab = A + (size_t)blockIdx.y*128*K;
    const float* Bb = Bw + blockIdx.x*128;

    int arow[4], acol[4];
#pragma unroll
    for (int i=0;i<4;i++) { int idx = tid + i*256; arow[i] = idx >> 3; acol[i] = (idx & 7)*4; }
    int bn[8], bkp[8];
#pragma unroll
    for (int i=0;i<8;i++) { int idx = tid + i*256; bn[i] = idx & 127; bkp[i] = idx >> 7; }

    float4 ra[4];
    float  rb0[8], rb1[8];

    auto gload = [&](int k0) {
#pragma unroll
        for (int i=0;i<4;i++)
            ra[i] = *(const float4*)&Ab[(size_t)arow[i]*K + k0 + acol[i]];
#pragma unroll
        for (int i=0;i<8;i++) {
            rb0[i] = Bb[(size_t)(k0 + 2*bkp[i] + 0)*N + bn[i]];
            rb1[i] = Bb[(size_t)(k0 + 2*bkp[i] + 1)*N + bn[i]];
        }
    };
    auto sstore = [&]() {
#pragma unroll
        for (int i=0;i<4;i++) {
            const float* v = (const float*)&ra[i];
            float h[4], l[4];
#pragma unroll
            for (int c=0;c<4;c++) {
                h[c] = __half2float(__float2half_rn(v[c]));
                l[c] = v[c] - h[c];
            }
            const int base = arow[i]*ST + (acol[i] >> 1);
            As_h[base+0] = f2h2(h[0], h[1]);
            As_h[base+1] = f2h2(h[2], h[3]);
            As_l[base+0] = f2h2(l[0], l[1]);
            As_l[base+1] = f2h2(l[2], l[3]);
        }
#pragma unroll
        for (int i=0;i<8;i++) {
            const float h0 = __half2float(__float2half_rn(rb0[i]));
            const float h1 = __half2float(__float2half_rn(rb1[i]));
            const int base = bn[i]*ST + bkp[i];
            Bs_h[base] = f2h2(h0, h1);
            Bs_l[base] = f2h2(rb0[i] - h0, rb1[i] - h1);
        }
    };

    gload(0);
    sstore();
    __syncthreads();

    for (int k0 = 0; k0 < K; k0 += 32) {
        const bool has_next = (k0 + 32) < K;
        if (has_next) gload(k0 + 32);

#pragma unroll
        for (int s = 0; s < 2; s++) {
            const int s8 = s*8;
            uint32_t ah[4][4], al[4][4];
#pragma unroll
            for (int mt=0; mt<4; mt++) {
                const int r0 = wm*64 + mt*16 + g;
                const int b0 = r0*ST + s8 + t4, b1 = (r0+8)*ST + s8 + t4;
                ah[mt][0] = As_h[b0];   ah[mt][1] = As_h[b1];
                ah[mt][2] = As_h[b0+4]; ah[mt][3] = As_h[b1+4];
                al[mt][0] = As_l[b0];   al[mt][1] = As_l[b1];
                al[mt][2] = As_l[b0+4]; al[mt][3] = As_l[b1+4];
            }
            uint32_t bh[4][2], bl[4][2];
#pragma unroll
            for (int nt=0; nt<4; nt++) {
                const int c = wn*32 + nt*8 + g;
                const int bb = c*ST + s8 + t4;
                bh[nt][0] = Bs_h[bb]; bh[nt][1] = Bs_h[bb+4];
                bl[nt][0] = Bs_l[bb]; bl[nt][1] = Bs_l[bb+4];
            }
#pragma unroll
            for (int mt=0; mt<4; mt++)
#pragma unroll
                for (int nt=0; nt<4; nt++) {
                    mma_f16(acc[mt][nt], al[mt], bh[nt]);   // lo*hi
                    mma_f16(acc[mt][nt], ah[mt], bl[nt]);   // hi*lo
                    mma_f16(acc[mt][nt], ah[mt], bh[nt]);   // hi*hi
                }
        }

        if (has_next) {
            __syncthreads();
            sstore();
            __syncthreads();
        }
    }

    // Epilogue: bias + leaky, then octet sum over the 8 rows (lane stride 4)
    // via bfly shuffles; lanes with g==0 store the two octet rows.
#pragma unroll
    for (int mt=0; mt<4; mt++) {
#pragma unroll
        for (int nt=0; nt<4; nt++) {
            const int c = blockIdx.x*128 + wn*32 + nt*8 + t4*2;
            const float b0 = bias[c], b1 = bias[c+1];
            float v00 = acc[mt][nt][0] + b0;
            float v01 = acc[mt][nt][1] + b1;
            float v10 = acc[mt][nt][2] + b0;
            float v11 = acc[mt][nt][3] + b1;
            v00 = (v00 > 0.f) ? v00 : 0.01f*v00;
            v01 = (v01 > 0.f) ? v01 : 0.01f*v01;
            v10 = (v10 > 0.f) ? v10 : 0.01f*v10;
            v11 = (v11 > 0.f) ? v11 : 0.01f*v11;
#pragma unroll
            for (int mask = 4; mask <= 16; mask <<= 1) {
                v00 += __shfl_xor_sync(0xffffffffu, v00, mask);
                v01 += __shfl_xor_sync(0xffffffffu, v01, mask);
                v10 += __shfl_xor_sync(0xffffffffu, v10, mask);
                v11 += __shfl_xor_sync(0xffffffffu, v11, mask);
            }
            if (lane < 4) {
                const size_t o0 = (size_t)blockIdx.y*16 + wm*8 + 2*mt;
                float2 s0; s0.x = v00; s0.y = v01;
                float2 s1; s1.x = v10; s1.y = v11;
                *(float2*)&S[o0*D1_ + c]       = s0;
                *(float2*)&S[(o0+1)*D1_ + c]   = s1;
            }
        }
    }
}

// ---------------------------------------------------------------------------
// pp[n] = ((S[oct h] + S[oct h+1]) / 16) @ W2 + b2   (patch = two octets)
// Block handles 8 patch rows; S is L2-resident (8.4 MB).
// ---------------------------------------------------------------------------
__global__ void __launch_bounds__(256)
pp_kernel(const float* __restrict__ S, const float* __restrict__ W2,
          const float* __restrict__ b2, float* __restrict__ pp)
{
    __shared__ float sP[8][D1_];
    const int tid = threadIdx.x;

#pragma unroll
    for (int rr = 0; rr < 8; rr++) {
        const int n = blockIdx.x*8 + rr;
        const int b = n / H_, h = n % H_;
        const float* s0 = S + ((size_t)b*512 + h)*D1_;
        sP[rr][tid] = (s0[tid] + s0[D1_ + tid]) * (1.f/16.f);
    }
    __syncthreads();

    const int i = tid & 63;
#pragma unroll
    for (int rr = tid >> 6; rr < 8; rr += 4) {
        float acc = b2[i];
#pragma unroll
        for (int j = 0; j < D1_; j++) acc += sP[rr][j] * W2[j*DF_ + i];
        pp[(blockIdx.x*8 + rr)*DF_ + i] = acc;
    }
}

// ---------------------------------------------------------------------------
// Fused per-row attention, 4 rows per 256-thread block.
// Branchless top-8 on raw scores (tanh monotone; zero/negative ties are
// value-irrelevant): orderable u32 keys with inverted index in low 6 bits,
// sorted 8-reg heap via unconditional compare-swaps. Winners' scores
// recomputed exactly; tanh on positives only.
// ---------------------------------------------------------------------------
__global__ void __launch_bounds__(256)
attn_kernel(const float* __restrict__ pp,
            const float* __restrict__ Wq, const float* __restrict__ Wk,
            const float* __restrict__ Wv,
            const float* __restrict__ Wagg, const float* __restrict__ bagg,
            float* __restrict__ z)
{
    const int r = threadIdx.x >> 6;      // row within block (0..3)
    const int i = threadIdx.x & 63;      // feature index
    const int n = blockIdx.x*4 + r;

    __shared__ float sp[4][DF_], sq[4][DF_], sk[4][DF_], sv[4][DF_], sAv[4][DF_];

    sp[r][i] = pp[n*DF_ + i];
    __syncthreads();

    float q = 0.f, k = 0.f, v = 0.f;
#pragma unroll
    for (int j = 0; j < DF_; j++) {
        const float x = sp[r][j];
        q += x * Wq[j*DF_ + i];
        k += x * Wk[j*DF_ + i];
        v += x * Wv[j*DF_ + i];
    }
    sq[r][i] = q; sk[r][i] = k; sv[r][i] = v;
    __syncthreads();

    float nq = 0.f, nk = 0.f;
#pragma unroll
    for (int j = 0; j < DF_; j++) { nq += sq[r][j]*sq[r][j]; nk += sk[r][j]*sk[r][j]; }
    const float inv_nq = 1.f / (sqrtf(nq) + EPS_);
    const float inv_nk = 1.f / (sqrtf(nk) + EPS_);

    const float c1 = (sq[r][i]*inv_nq) * inv_nk;
    const float c2 = (sk[r][i]*inv_nk) * inv_nq;

    uint32_t h[8];
#pragma unroll
    for (int t = 0; t < 8; t++) h[t] = 0u;

#pragma unroll
    for (int j = 0; j < DF_; j++) {
        const float s = c1*sk[r][j] - c2*sq[r][j];
        uint32_t u = __float_as_uint(s);
        u = ((int32_t)u < 0) ? ~u : (u | 0x80000000u);
        u = (u & 0xFFFFFFC0u) | (uint32_t)(63 - j);
        h[0] = (h[0] > u) ? h[0] : u;      // replace current min if larger
#pragma unroll
        for (int t = 0; t < 7; t++) {      // single bubble pass re-sorts
            const uint32_t lo = (h[t] < h[t+1]) ? h[t] : h[t+1];
            const uint32_t hi = (h[t] < h[t+1]) ? h[t+1] : h[t];
            h[t] = lo; h[t+1] = hi;
        }
    }

    float sum8 = 0.f, av = 0.f;
#pragma unroll
    for (int t = 0; t < 8; t++) {
        const int j = 63 - (int)(h[t] & 63u);
        const float s = c1*sk[r][j] - c2*sq[r][j];
        if (s > 0.f) {
            const float e = __expf(2.f*s);
            const float a = 1.f - __fdividef(2.f, e + 1.f);   // tanh(s)
            sum8 += a;
            av   += a * sv[r][j];
        }
    }
    av *= 1.f / fmaxf(sum8, EPS_);

    sAv[r][i] = av;
    __syncthreads();

    float acc = bagg[i];
#pragma unroll
    for (int j = 0; j < DF_; j++) acc += sAv[r][j]*Wagg[j*DF_ + i];
    z[n*DF_ + i] = (acc > 0.f) ? acc : 0.01f*acc;
}

// ---------------------------------------------------------------------------
// zd = z @ Wdec  (8176 x 64 x 512, FFMA; Wdec staged in smem per 16-row block)
// ---------------------------------------------------------------------------
__global__ void __launch_bounds__(256)
zdec_kernel(const float* __restrict__ z, const float* __restrict__ Wdec,
            float* __restrict__ zd)
{
    __shared__ float zs[16*DF_];
    __shared__ float ws[DF_*132];
    const int tid = threadIdx.x;
    const int n0 = blockIdx.x*16;

    {
        const int r = tid >> 4, c4 = (tid & 15)*4;
        *(float4*)&zs[r*DF_ + c4] = *(const float4*)&z[(size_t)(n0+r)*DF_ + c4];
    }

    const int ct64 = tid & 63;
    const int rt   = tid >> 6;

    for (int ct = 0; ct < 4; ct++) {
        __syncthreads();
#pragma unroll
        for (int i = 0; i < 8; i++) {
            const int idx = tid + i*256;            // 0..2047 float4
            const int r = idx >> 5, c4 = (idx & 31)*4;
            *(float4*)&ws[r*132 + c4] = *(const float4*)&Wdec[(size_t)r*D_ + ct*128 + c4];
        }
        __syncthreads();

        float acc[4][2];
#pragma unroll
        for (int r=0;r<4;r++) { acc[r][0]=0.f; acc[r][1]=0.f; }
#pragma unroll
        for (int k = 0; k < DF_; k++) {
            const float2 w = *(const float2*)&ws[k*132 + ct64*2];
#pragma unroll
            for (int r = 0; r < 4; r++) {
                const float zv = zs[(rt*4+r)*DF_ + k];
                acc[r][0] += zv*w.x;
                acc[r][1] += zv*w.y;
            }
        }
#pragma unroll
        for (int r = 0; r < 4; r++) {
            float2 o; o.x = acc[r][0]; o.y = acc[r][1];
            *(float2*)&zd[(size_t)(n0 + rt*4 + r)*D_ + ct*128 + ct64*2] = o;
        }
    }
}

// ---------------------------------------------------------------------------
// Final overlap-add in decoder space: out = overlap(zd)/cnt + bdec
// ---------------------------------------------------------------------------
__global__ void overlap2_kernel(const float* __restrict__ zd,
                                const float* __restrict__ bdec,
                                float* __restrict__ out)
{
    const int idx = blockIdx.x*blockDim.x + threadIdx.x;   // over M_*D_
    const int c = idx & 511;
    const int l = (idx >> 9) & 4095;
    const int b = idx >> 21;

    int hlo = (l >= 15) ? (l - 8) / 8 : 0;
    int hhi = l / 8; if (hhi > H_-1) hhi = H_-1;

    float s = 0.f;
    for (int hh = hlo; hh <= hhi; hh++)
        s += zd[((size_t)b*H_ + hh)*D_ + c];
    out[idx] = s / (float)(hhi - hlo + 1) + bdec[c];
}

// ---------------------------------------------------------------------------
extern "C" void kernel_launch(void* const* d_in, const int* in_sizes, int n_in,
                              void* d_out, int out_size)
{
    const float* X    = (const float*)d_in[0];
    const float* W1   = (const float*)d_in[1];
    const float* b1   = (const float*)d_in[2];
    const float* W2   = (const float*)d_in[3];
    const float* b2   = (const float*)d_in[4];
    const float* Wq   = (const float*)d_in[5];
    const float* Wk   = (const float*)d_in[6];
    const float* Wv   = (const float*)d_in[7];
    const float* Wagg = (const float*)d_in[8];
    const float* bagg = (const float*)d_in[9];
    const float* Wdec = (const float*)d_in[10];
    const float* bdec = (const float*)d_in[11];
    float* out = (float*)d_out;

    float *S, *pp, *z, *zd;
    cudaGetSymbolAddress((void**)&S,  g_S);
    cudaGetSymbolAddress((void**)&pp, g_pp);
    cudaGetSymbolAddress((void**)&z,  g_z);
    cudaGetSymbolAddress((void**)&zd, g_zd);

    // 1) S = octet-sums of leaky(X @ W1 + b1)   (fp16-split MMA, fused epi)
    gemm_h<<<dim3(D1_/128, M_/128), 256>>>(X, W1, b1, S, M_, D_, D1_);

    // 2) pp = ((S[h] + S[h+1]) / 16) @ W2 + b2   [8176,256]x[256,64]
    pp_kernel<<<NROWS/8, 256>>>(S, W2, b2, pp);

    // 3) fused qkv + attention + top-8 + aggregate (4 rows / block)
    attn_kernel<<<NROWS/4, 256>>>(pp, Wq, Wk, Wv, Wagg, bagg, z);

    // 4) zd = z @ Wdec              [8176,64]x[64,512]
    zdec_kernel<<<NROWS/16, 256>>>(z, Wdec, zd);

    // 5) out = overlap(zd)/cnt + bdec
    overlap2_kernel<<<(M_*D_)/256, 256>>>(zd, bdec, out);
}

// round 11
// speedup vs baseline: 2.4410x; 1.3637x over previous
#include <cuda_runtime.h>
#include <cuda_fp16.h>
#include <cstdint>

// Problem constants
#define B_    16
#define L_    4096
#define D_    512
#define D1_   256
#define DF_   64
#define H_    511            // (4096-16)/8 + 1
#define NROWS (B_*H_)        // 8176
#define M_    (B_*L_)        // 65536
#define NOCT  (M_/8)         // 8192 octet rows (512 per batch)
#define EPS_  1e-8f

// Scratch (no allocations allowed)
__device__ float g_S [(size_t)NOCT*D1_];     // octet sums of leaky(X@W1+b1)
__device__ float g_pp[NROWS*DF_];            // per-patch encodings
__device__ float g_z [NROWS*DF_];            // aggregated
__device__ float g_zd[(size_t)NROWS*D_];     // z @ Wdec

// ---------------------------------------------------------------------------
// fp16 helpers
// ---------------------------------------------------------------------------
__device__ __forceinline__ uint32_t f2h2(float a, float b) {
    __half2 h = __floats2half2_rn(a, b);
    return *reinterpret_cast<uint32_t*>(&h);
}
__device__ __forceinline__ void mma_f16(float* d, const uint32_t* a, const uint32_t* b) {
    asm volatile(
        "mma.sync.aligned.m16n8k16.row.col.f32.f16.f16.f32 "
        "{%0,%1,%2,%3}, {%4,%5,%6,%7}, {%8,%9}, {%0,%1,%2,%3};"
        : "+f"(d[0]), "+f"(d[1]), "+f"(d[2]), "+f"(d[3])
        : "r"(a[0]), "r"(a[1]), "r"(a[2]), "r"(a[3]), "r"(b[0]), "r"(b[1]));
}
__device__ __forceinline__ void ldsm_x4(uint32_t* r, uint32_t addr) {
    asm volatile("ldmatrix.sync.aligned.m8n8.x4.shared.b16 {%0,%1,%2,%3}, [%4];"
        : "=r"(r[0]), "=r"(r[1]), "=r"(r[2]), "=r"(r[3]) : "r"(addr));
}
__device__ __forceinline__ void ldsm_x4_t(uint32_t* r, uint32_t addr) {
    asm volatile("ldmatrix.sync.aligned.m8n8.x4.trans.shared.b16 {%0,%1,%2,%3}, [%4];"
        : "=r"(r[0]), "=r"(r[1]), "=r"(r[2]), "=r"(r[3]) : "r"(addr));
}

// ---------------------------------------------------------------------------
// Split-FP16 tensor-core GEMM1 with fused octet-sum epilogue:
//   S[oct, col] = sum_{8 rows of oct} leaky(X@W1 + b1)
// BM=BN=128, BK=32, 256 threads (8 warps 2x4), warp tile 64x32.
// v = hi + lo fp16 split; 3 MMA products (hh, hl, lh), fp32 accumulate.
// A smem: [row][kpair] half2, row stride 20 u32 (bank-quads 5r%8: distinct).
// B smem: [k][n] halves, row stride 272 B (17 quads: distinct) -> x4.trans
// gives the mma B fragment directly. Ping-pong double buffer, 1 sync/block.
// Epilogue: octet sums via 3 bfly shuffles (rows at lane stride 4).
// ---------------------------------------------------------------------------
#define AST_B   80          // A row stride, bytes
#define BST_B   272         // B row stride, bytes
#define OFF_AL  10240       // 128*80
#define OFF_BH  20480
#define OFF_BL  29184       // +32*272
#define BUFSZ   37888       // per ping-pong buffer
#define GEMM_SMEM (2*BUFSZ) // 75776

__global__ void __launch_bounds__(256)
gemm_h(const float* __restrict__ A, const float* __restrict__ Bw,
       const float* __restrict__ bias, float* __restrict__ S,
       int M, int K, int N)
{
    extern __shared__ char smem[];
    const uint32_t sb = (uint32_t)__cvta_generic_to_shared(smem);

    const int tid  = threadIdx.x;
    const int warp = tid >> 5, lane = tid & 31;
    const int wm = warp >> 2, wn = warp & 3;

    float acc[4][4][4];
#pragma unroll
    for (int mt=0; mt<4; mt++)
#pragma unroll
        for (int nt=0; nt<4; nt++)
#pragma unroll
            for (int c=0; c<4; c++) acc[mt][nt][c] = 0.f;

    const float* Ab = A + (size_t)blockIdx.y*128*K;
    const float* Bb = Bw + blockIdx.x*128;

    // global-load index maps
    int arow[4], acol[4];
#pragma unroll
    for (int i=0;i<4;i++) { int idx = tid + i*256; arow[i] = idx >> 3; acol[i] = (idx & 7)*4; }
    int bk[4], bn4[4];
#pragma unroll
    for (int i=0;i<4;i++) { int idx = tid + i*256; bk[i] = idx >> 5; bn4[i] = (idx & 31)*4; }

    // ldmatrix lane address bases (byte offsets within a buffer)
    const uint32_t aBase = sb + (uint32_t)((wm*64 + (lane & 15))*AST_B + ((lane >> 4)*16));
    const uint32_t bBase = sb + OFF_BH
        + (uint32_t)(((lane & 7) + ((lane >> 4) & 1)*8)*BST_B
                     + (wn*32 + ((lane >> 3) & 1)*8)*2);

    float4 ra[4], rb[4];

    auto gload = [&](int k0) {
#pragma unroll
        for (int i=0;i<4;i++)
            ra[i] = *(const float4*)&Ab[(size_t)arow[i]*K + k0 + acol[i]];
#pragma unroll
        for (int i=0;i<4;i++)
            rb[i] = *(const float4*)&Bb[(size_t)(k0 + bk[i])*N + bn4[i]];
    };
    auto sstore = [&](int bo) {
#pragma unroll
        for (int i=0;i<4;i++) {
            const float* v = (const float*)&ra[i];
            float h0 = __half2float(__float2half_rn(v[0]));
            float h1 = __half2float(__float2half_rn(v[1]));
            float h2 = __half2float(__float2half_rn(v[2]));
            float h3 = __half2float(__float2half_rn(v[3]));
            uint2 hh; hh.x = f2h2(h0, h1);       hh.y = f2h2(h2, h3);
            uint2 ll; ll.x = f2h2(v[0]-h0, v[1]-h1); ll.y = f2h2(v[2]-h2, v[3]-h3);
            const int byte = arow[i]*AST_B + acol[i]*2;
            *(uint2*)(smem + bo + byte)          = hh;
            *(uint2*)(smem + bo + OFF_AL + byte) = ll;
        }
#pragma unroll
        for (int i=0;i<4;i++) {
            const float* v = (const float*)&rb[i];
            float h0 = __half2float(__float2half_rn(v[0]));
            float h1 = __half2float(__float2half_rn(v[1]));
            float h2 = __half2float(__float2half_rn(v[2]));
            float h3 = __half2float(__float2half_rn(v[3]));
            uint2 hh; hh.x = f2h2(h0, h1);       hh.y = f2h2(h2, h3);
            uint2 ll; ll.x = f2h2(v[0]-h0, v[1]-h1); ll.y = f2h2(v[2]-h2, v[3]-h3);
            const int byte = bk[i]*BST_B + bn4[i]*2;
            *(uint2*)(smem + bo + OFF_BH + byte) = hh;
            *(uint2*)(smem + bo + OFF_BL + byte) = ll;
        }
    };

    gload(0);
    sstore(0);
    __syncthreads();

    int bo = 0;
    for (int k0 = 0; k0 < K; k0 += 32) {
        const bool has_next = (k0 + 32) < K;
        if (has_next) gload(k0 + 32);

#pragma unroll
        for (int s = 0; s < 2; s++) {
            uint32_t ah[4][4], al[4][4];
#pragma unroll
            for (int mt=0; mt<4; mt++) {
                const uint32_t aa = aBase + bo + mt*1280 + s*32;
                ldsm_x4(ah[mt], aa);
                ldsm_x4(al[mt], aa + OFF_AL);
            }
            uint32_t bh[4][2], bl[4][2];
            {
                uint32_t t[4];
                const uint32_t ba = bBase + bo + s*4352;
                ldsm_x4_t(t, ba);
                bh[0][0]=t[0]; bh[0][1]=t[2]; bh[1][0]=t[1]; bh[1][1]=t[3];
                ldsm_x4_t(t, ba + 32);
                bh[2][0]=t[0]; bh[2][1]=t[2]; bh[3][0]=t[1]; bh[3][1]=t[3];
                ldsm_x4_t(t, ba + (OFF_BL - OFF_BH));
                bl[0][0]=t[0]; bl[0][1]=t[2]; bl[1][0]=t[1]; bl[1][1]=t[3];
                ldsm_x4_t(t, ba + (OFF_BL - OFF_BH) + 32);
                bl[2][0]=t[0]; bl[2][1]=t[2]; bl[3][0]=t[1]; bl[3][1]=t[3];
            }
#pragma unroll
            for (int mt=0; mt<4; mt++)
#pragma unroll
                for (int nt=0; nt<4; nt++) {
                    mma_f16(acc[mt][nt], al[mt], bh[nt]);   // lo*hi
                    mma_f16(acc[mt][nt], ah[mt], bl[nt]);   // hi*lo
                    mma_f16(acc[mt][nt], ah[mt], bh[nt]);   // hi*hi
                }
        }

        if (has_next) sstore(bo ^ BUFSZ);
        __syncthreads();
        bo ^= BUFSZ;
    }

    // Epilogue: bias + leaky, octet sums via bfly shuffles, lanes<4 store.
    const int t4 = lane & 3;
#pragma unroll
    for (int mt=0; mt<4; mt++) {
#pragma unroll
        for (int nt=0; nt<4; nt++) {
            const int c = blockIdx.x*128 + wn*32 + nt*8 + t4*2;
            const float b0 = bias[c], b1 = bias[c+1];
            float v00 = acc[mt][nt][0] + b0;
            float v01 = acc[mt][nt][1] + b1;
            float v10 = acc[mt][nt][2] + b0;
            float v11 = acc[mt][nt][3] + b1;
            v00 = (v00 > 0.f) ? v00 : 0.01f*v00;
            v01 = (v01 > 0.f) ? v01 : 0.01f*v01;
            v10 = (v10 > 0.f) ? v10 : 0.01f*v10;
            v11 = (v11 > 0.f) ? v11 : 0.01f*v11;
#pragma unroll
            for (int mask = 4; mask <= 16; mask <<= 1) {
                v00 += __shfl_xor_sync(0xffffffffu, v00, mask);
                v01 += __shfl_xor_sync(0xffffffffu, v01, mask);
                v10 += __shfl_xor_sync(0xffffffffu, v10, mask);
                v11 += __shfl_xor_sync(0xffffffffu, v11, mask);
            }
            if (lane < 4) {
                const size_t o0 = (size_t)blockIdx.y*16 + wm*8 + 2*mt;
                float2 s0; s0.x = v00; s0.y = v01;
                float2 s1; s1.x = v10; s1.y = v11;
                *(float2*)&S[o0*D1_ + c]     = s0;
                *(float2*)&S[(o0+1)*D1_ + c] = s1;
            }
        }
    }
}

// ---------------------------------------------------------------------------
// pp[n] = ((S[oct h] + S[oct h+1]) / 16) @ W2 + b2   (patch = two octets)
// ---------------------------------------------------------------------------
__global__ void __launch_bounds__(256)
pp_kernel(const float* __restrict__ S, const float* __restrict__ W2,
          const float* __restrict__ b2, float* __restrict__ pp)
{
    __shared__ float sP[8][D1_];
    const int tid = threadIdx.x;

#pragma unroll
    for (int rr = 0; rr < 8; rr++) {
        const int n = blockIdx.x*8 + rr;
        const int b = n / H_, h = n % H_;
        const float* s0 = S + ((size_t)b*512 + h)*D1_;
        sP[rr][tid] = (s0[tid] + s0[D1_ + tid]) * (1.f/16.f);
    }
    __syncthreads();

    const int i = tid & 63;
#pragma unroll
    for (int rr = tid >> 6; rr < 8; rr += 4) {
        float acc = b2[i];
#pragma unroll
        for (int j = 0; j < D1_; j++) acc += sP[rr][j] * W2[j*DF_ + i];
        pp[(blockIdx.x*8 + rr)*DF_ + i] = acc;
    }
}

// ---------------------------------------------------------------------------
// Fused per-row attention, 4 rows per 256-thread block (branchless top-8).
// ---------------------------------------------------------------------------
__global__ void __launch_bounds__(256)
attn_kernel(const float* __restrict__ pp,
            const float* __restrict__ Wq, const float* __restrict__ Wk,
            const float* __restrict__ Wv,
            const float* __restrict__ Wagg, const float* __restrict__ bagg,
            float* __restrict__ z)
{
    const int r = threadIdx.x >> 6;
    const int i = threadIdx.x & 63;
    const int n = blockIdx.x*4 + r;

    __shared__ float sp[4][DF_], sq[4][DF_], sk[4][DF_], sv[4][DF_], sAv[4][DF_];

    sp[r][i] = pp[n*DF_ + i];
    __syncthreads();

    float q = 0.f, k = 0.f, v = 0.f;
#pragma unroll
    for (int j = 0; j < DF_; j++) {
        const float x = sp[r][j];
        q += x * Wq[j*DF_ + i];
        k += x * Wk[j*DF_ + i];
        v += x * Wv[j*DF_ + i];
    }
    sq[r][i] = q; sk[r][i] = k; sv[r][i] = v;
    __syncthreads();

    float nq = 0.f, nk = 0.f;
#pragma unroll
    for (int j = 0; j < DF_; j++) { nq += sq[r][j]*sq[r][j]; nk += sk[r][j]*sk[r][j]; }
    const float inv_nq = 1.f / (sqrtf(nq) + EPS_);
    const float inv_nk = 1.f / (sqrtf(nk) + EPS_);

    const float c1 = (sq[r][i]*inv_nq) * inv_nk;
    const float c2 = (sk[r][i]*inv_nk) * inv_nq;

    uint32_t h[8];
#pragma unroll
    for (int t = 0; t < 8; t++) h[t] = 0u;

#pragma unroll
    for (int j = 0; j < DF_; j++) {
        const float s = c1*sk[r][j] - c2*sq[r][j];
        uint32_t u = __float_as_uint(s);
        u = ((int32_t)u < 0) ? ~u : (u | 0x80000000u);
        u = (u & 0xFFFFFFC0u) | (uint32_t)(63 - j);
        h[0] = (h[0] > u) ? h[0] : u;
#pragma unroll
        for (int t = 0; t < 7; t++) {
            const uint32_t lo = (h[t] < h[t+1]) ? h[t] : h[t+1];
            const uint32_t hi = (h[t] < h[t+1]) ? h[t+1] : h[t];
            h[t] = lo; h[t+1] = hi;
        }
    }

    float sum8 = 0.f, av = 0.f;
#pragma unroll
    for (int t = 0; t < 8; t++) {
        const int j = 63 - (int)(h[t] & 63u);
        const float s = c1*sk[r][j] - c2*sq[r][j];
        if (s > 0.f) {
            const float e = __expf(2.f*s);
            const float a = 1.f - __fdividef(2.f, e + 1.f);
            sum8 += a;
            av   += a * sv[r][j];
        }
    }
    av *= 1.f / fmaxf(sum8, EPS_);

    sAv[r][i] = av;
    __syncthreads();

    float acc = bagg[i];
#pragma unroll
    for (int j = 0; j < DF_; j++) acc += sAv[r][j]*Wagg[j*DF_ + i];
    z[n*DF_ + i] = (acc > 0.f) ? acc : 0.01f*acc;
}

// ---------------------------------------------------------------------------
// zd = z @ Wdec  (8176 x 64 x 512, FFMA)
// ---------------------------------------------------------------------------
__global__ void __launch_bounds__(256)
zdec_kernel(const float* __restrict__ z, const float* __restrict__ Wdec,
            float* __restrict__ zd)
{
    __shared__ float zs[16*DF_];
    __shared__ float ws[DF_*132];
    const int tid = threadIdx.x;
    const int n0 = blockIdx.x*16;

    {
        const int r = tid >> 4, c4 = (tid & 15)*4;
        *(float4*)&zs[r*DF_ + c4] = *(const float4*)&z[(size_t)(n0+r)*DF_ + c4];
    }

    const int ct64 = tid & 63;
    const int rt   = tid >> 6;

    for (int ct = 0; ct < 4; ct++) {
        __syncthreads();
#pragma unroll
        for (int i = 0; i < 8; i++) {
            const int idx = tid + i*256;
            const int r = idx >> 5, c4 = (idx & 31)*4;
            *(float4*)&ws[r*132 + c4] = *(const float4*)&Wdec[(size_t)r*D_ + ct*128 + c4];
        }
        __syncthreads();

        float acc[4][2];
#pragma unroll
        for (int r=0;r<4;r++) { acc[r][0]=0.f; acc[r][1]=0.f; }
#pragma unroll
        for (int k = 0; k < DF_; k++) {
            const float2 w = *(const float2*)&ws[k*132 + ct64*2];
#pragma unroll
            for (int r = 0; r < 4; r++) {
                const float zv = zs[(rt*4+r)*DF_ + k];
                acc[r][0] += zv*w.x;
                acc[r][1] += zv*w.y;
            }
        }
#pragma unroll
        for (int r = 0; r < 4; r++) {
            float2 o; o.x = acc[r][0]; o.y = acc[r][1];
            *(float2*)&zd[(size_t)(n0 + rt*4 + r)*D_ + ct*128 + ct64*2] = o;
        }
    }
}

// ---------------------------------------------------------------------------
// Final overlap-add in decoder space (vectorized): out = overlap(zd)/cnt + bdec
// ---------------------------------------------------------------------------
__global__ void overlap2_kernel(const float* __restrict__ zd,
                                const float* __restrict__ bdec,
                                float* __restrict__ out)
{
    const int idx = blockIdx.x*blockDim.x + threadIdx.x;   // over M_*D_/4
    const int c4 = (idx & 127)*4;
    const int l  = (idx >> 7) & 4095;
    const int b  = idx >> 19;

    int hlo = (l >= 15) ? (l - 8) / 8 : 0;
    int hhi = l / 8; if (hhi > H_-1) hhi = H_-1;

    float4 s = *(const float4*)&zd[((size_t)b*H_ + hlo)*D_ + c4];
    if (hhi != hlo) {
        const float4 s2 = *(const float4*)&zd[((size_t)b*H_ + hhi)*D_ + c4];
        s.x = (s.x + s2.x)*0.5f; s.y = (s.y + s2.y)*0.5f;
        s.z = (s.z + s2.z)*0.5f; s.w = (s.w + s2.w)*0.5f;
    }
    const float4 bb = *(const float4*)&bdec[c4];
    s.x += bb.x; s.y += bb.y; s.z += bb.z; s.w += bb.w;
    *(float4*)&out[(size_t)idx*4] = s;
}

// ---------------------------------------------------------------------------
extern "C" void kernel_launch(void* const* d_in, const int* in_sizes, int n_in,
                              void* d_out, int out_size)
{
    const float* X    = (const float*)d_in[0];
    const float* W1   = (const float*)d_in[1];
    const float* b1   = (const float*)d_in[2];
    const float* W2   = (const float*)d_in[3];
    const float* b2   = (const float*)d_in[4];
    const float* Wq   = (const float*)d_in[5];
    const float* Wk   = (const float*)d_in[6];
    const float* Wv   = (const float*)d_in[7];
    const float* Wagg = (const float*)d_in[8];
    const float* bagg = (const float*)d_in[9];
    const float* Wdec = (const float*)d_in[10];
    const float* bdec = (const float*)d_in[11];
    float* out = (float*)d_out;

    float *S, *pp, *z, *zd;
    cudaGetSymbolAddress((void**)&S,  g_S);
    cudaGetSymbolAddress((void**)&pp, g_pp);
    cudaGetSymbolAddress((void**)&z,  g_z);
    cudaGetSymbolAddress((void**)&zd, g_zd);

    cudaFuncSetAttribute(gemm_h,
        cudaFuncAttributeMaxDynamicSharedMemorySize, GEMM_SMEM);

    // 1) S = octet-sums of leaky(X @ W1 + b1)   (fp16-split MMA, ldmatrix)
    gemm_h<<<dim3(D1_/128, M_/128), 256, GEMM_SMEM>>>(X, W1, b1, S, M_, D_, D1_);

    // 2) pp = ((S[h] + S[h+1]) / 16) @ W2 + b2
    pp_kernel<<<NROWS/8, 256>>>(S, W2, b2, pp);

    // 3) fused qkv + attention + top-8 + aggregate
    attn_kernel<<<NROWS/4, 256>>>(pp, Wq, Wk, Wv, Wagg, bagg, z);

    // 4) zd = z @ Wdec
    zdec_kernel<<<NROWS/16, 256>>>(z, Wdec, zd);

    // 5) out = overlap(zd)/cnt + bdec   (float4)
    overlap2_kernel<<<(M_*D_)/1024, 256>>>(zd, bdec, out);
}

// round 12
// speedup vs baseline: 2.5881x; 1.0602x over previous
#include <cuda_runtime.h>
#include <cuda_fp16.h>
#include <cstdint>

// Problem constants
#define B_    16
#define L_    4096
#define D_    512
#define D1_   256
#define DF_   64
#define H_    511            // (4096-16)/8 + 1
#define NROWS (B_*H_)        // 8176
#define M_    (B_*L_)        // 65536
#define NOCT  (M_/8)         // 8192 octet rows (512 per batch)
#define EPS_  1e-8f

// Scratch (no allocations allowed)
__device__ float g_S [(size_t)NOCT*D1_];     // octet sums of leaky(X@W1+b1)
__device__ float g_pp[NROWS*DF_];            // per-patch encodings
__device__ float g_z [NROWS*DF_];            // aggregated

// ---------------------------------------------------------------------------
// fp16 helpers
// ---------------------------------------------------------------------------
__device__ __forceinline__ uint32_t f2h2(float a, float b) {
    __half2 h = __floats2half2_rn(a, b);
    return *reinterpret_cast<uint32_t*>(&h);
}
__device__ __forceinline__ void mma_f16(float* d, const uint32_t* a, const uint32_t* b) {
    asm volatile(
        "mma.sync.aligned.m16n8k16.row.col.f32.f16.f16.f32 "
        "{%0,%1,%2,%3}, {%4,%5,%6,%7}, {%8,%9}, {%0,%1,%2,%3};"
        : "+f"(d[0]), "+f"(d[1]), "+f"(d[2]), "+f"(d[3])
        : "r"(a[0]), "r"(a[1]), "r"(a[2]), "r"(a[3]), "r"(b[0]), "r"(b[1]));
}
__device__ __forceinline__ void ldsm_x4(uint32_t* r, uint32_t addr) {
    asm volatile("ldmatrix.sync.aligned.m8n8.x4.shared.b16 {%0,%1,%2,%3}, [%4];"
        : "=r"(r[0]), "=r"(r[1]), "=r"(r[2]), "=r"(r[3]) : "r"(addr));
}
__device__ __forceinline__ void ldsm_x4_t(uint32_t* r, uint32_t addr) {
    asm volatile("ldmatrix.sync.aligned.m8n8.x4.trans.shared.b16 {%0,%1,%2,%3}, [%4];"
        : "=r"(r[0]), "=r"(r[1]), "=r"(r[2]), "=r"(r[3]) : "r"(addr));
}

// ---------------------------------------------------------------------------
// Split-FP16 tensor-core GEMM1 with fused octet-sum epilogue (unchanged R11):
//   S[oct, col] = sum_{8 rows of oct} leaky(X@W1 + b1)
// ---------------------------------------------------------------------------
#define AST_B   80          // A row stride, bytes
#define BST_B   272         // B row stride, bytes
#define OFF_AL  10240       // 128*80
#define OFF_BH  20480
#define OFF_BL  29184       // +32*272
#define BUFSZ   37888       // per ping-pong buffer
#define GEMM_SMEM (2*BUFSZ) // 75776

__global__ void __launch_bounds__(256)
gemm_h(const float* __restrict__ A, const float* __restrict__ Bw,
       const float* __restrict__ bias, float* __restrict__ S,
       int M, int K, int N)
{
    extern __shared__ char smem[];
    const uint32_t sb = (uint32_t)__cvta_generic_to_shared(smem);

    const int tid  = threadIdx.x;
    const int warp = tid >> 5, lane = tid & 31;
    const int wm = warp >> 2, wn = warp & 3;

    float acc[4][4][4];
#pragma unroll
    for (int mt=0; mt<4; mt++)
#pragma unroll
        for (int nt=0; nt<4; nt++)
#pragma unroll
            for (int c=0; c<4; c++) acc[mt][nt][c] = 0.f;

    const float* Ab = A + (size_t)blockIdx.y*128*K;
    const float* Bb = Bw + blockIdx.x*128;

    int arow[4], acol[4];
#pragma unroll
    for (int i=0;i<4;i++) { int idx = tid + i*256; arow[i] = idx >> 3; acol[i] = (idx & 7)*4; }
    int bk[4], bn4[4];
#pragma unroll
    for (int i=0;i<4;i++) { int idx = tid + i*256; bk[i] = idx >> 5; bn4[i] = (idx & 31)*4; }

    const uint32_t aBase = sb + (uint32_t)((wm*64 + (lane & 15))*AST_B + ((lane >> 4)*16));
    const uint32_t bBase = sb + OFF_BH
        + (uint32_t)(((lane & 7) + ((lane >> 4) & 1)*8)*BST_B
                     + (wn*32 + ((lane >> 3) & 1)*8)*2);

    float4 ra[4], rb[4];

    auto gload = [&](int k0) {
#pragma unroll
        for (int i=0;i<4;i++)
            ra[i] = *(const float4*)&Ab[(size_t)arow[i]*K + k0 + acol[i]];
#pragma unroll
        for (int i=0;i<4;i++)
            rb[i] = *(const float4*)&Bb[(size_t)(k0 + bk[i])*N + bn4[i]];
    };
    auto sstore = [&](int bo) {
#pragma unroll
        for (int i=0;i<4;i++) {
            const float* v = (const float*)&ra[i];
            float h0 = __half2float(__float2half_rn(v[0]));
            float h1 = __half2float(__float2half_rn(v[1]));
            float h2 = __half2float(__float2half_rn(v[2]));
            float h3 = __half2float(__float2half_rn(v[3]));
            uint2 hh; hh.x = f2h2(h0, h1);       hh.y = f2h2(h2, h3);
            uint2 ll; ll.x = f2h2(v[0]-h0, v[1]-h1); ll.y = f2h2(v[2]-h2, v[3]-h3);
            const int byte = arow[i]*AST_B + acol[i]*2;
            *(uint2*)(smem + bo + byte)          = hh;
            *(uint2*)(smem + bo + OFF_AL + byte) = ll;
        }
#pragma unroll
        for (int i=0;i<4;i++) {
            const float* v = (const float*)&rb[i];
            float h0 = __half2float(__float2half_rn(v[0]));
            float h1 = __half2float(__float2half_rn(v[1]));
            float h2 = __half2float(__float2half_rn(v[2]));
            float h3 = __half2float(__float2half_rn(v[3]));
            uint2 hh; hh.x = f2h2(h0, h1);       hh.y = f2h2(h2, h3);
            uint2 ll; ll.x = f2h2(v[0]-h0, v[1]-h1); ll.y = f2h2(v[2]-h2, v[3]-h3);
            const int byte = bk[i]*BST_B + bn4[i]*2;
            *(uint2*)(smem + bo + OFF_BH + byte) = hh;
            *(uint2*)(smem + bo + OFF_BL + byte) = ll;
        }
    };

    gload(0);
    sstore(0);
    __syncthreads();

    int bo = 0;
    for (int k0 = 0; k0 < K; k0 += 32) {
        const bool has_next = (k0 + 32) < K;
        if (has_next) gload(k0 + 32);

#pragma unroll
        for (int s = 0; s < 2; s++) {
            uint32_t ah[4][4], al[4][4];
#pragma unroll
            for (int mt=0; mt<4; mt++) {
                const uint32_t aa = aBase + bo + mt*1280 + s*32;
                ldsm_x4(ah[mt], aa);
                ldsm_x4(al[mt], aa + OFF_AL);
            }
            uint32_t bh[4][2], bl[4][2];
            {
                uint32_t t[4];
                const uint32_t ba = bBase + bo + s*4352;
                ldsm_x4_t(t, ba);
                bh[0][0]=t[0]; bh[0][1]=t[2]; bh[1][0]=t[1]; bh[1][1]=t[3];
                ldsm_x4_t(t, ba + 32);
                bh[2][0]=t[0]; bh[2][1]=t[2]; bh[3][0]=t[1]; bh[3][1]=t[3];
                ldsm_x4_t(t, ba + (OFF_BL - OFF_BH));
                bl[0][0]=t[0]; bl[0][1]=t[2]; bl[1][0]=t[1]; bl[1][1]=t[3];
                ldsm_x4_t(t, ba + (OFF_BL - OFF_BH) + 32);
                bl[2][0]=t[0]; bl[2][1]=t[2]; bl[3][0]=t[1]; bl[3][1]=t[3];
            }
#pragma unroll
            for (int mt=0; mt<4; mt++)
#pragma unroll
                for (int nt=0; nt<4; nt++) {
                    mma_f16(acc[mt][nt], al[mt], bh[nt]);   // lo*hi
                    mma_f16(acc[mt][nt], ah[mt], bl[nt]);   // hi*lo
                    mma_f16(acc[mt][nt], ah[mt], bh[nt]);   // hi*hi
                }
        }

        if (has_next) sstore(bo ^ BUFSZ);
        __syncthreads();
        bo ^= BUFSZ;
    }

    // Epilogue: bias + leaky, octet sums via bfly shuffles, lanes<4 store.
    const int t4 = lane & 3;
#pragma unroll
    for (int mt=0; mt<4; mt++) {
#pragma unroll
        for (int nt=0; nt<4; nt++) {
            const int c = blockIdx.x*128 + wn*32 + nt*8 + t4*2;
            const float b0 = bias[c], b1 = bias[c+1];
            float v00 = acc[mt][nt][0] + b0;
            float v01 = acc[mt][nt][1] + b1;
            float v10 = acc[mt][nt][2] + b0;
            float v11 = acc[mt][nt][3] + b1;
            v00 = (v00 > 0.f) ? v00 : 0.01f*v00;
            v01 = (v01 > 0.f) ? v01 : 0.01f*v01;
            v10 = (v10 > 0.f) ? v10 : 0.01f*v10;
            v11 = (v11 > 0.f) ? v11 : 0.01f*v11;
#pragma unroll
            for (int mask = 4; mask <= 16; mask <<= 1) {
                v00 += __shfl_xor_sync(0xffffffffu, v00, mask);
                v01 += __shfl_xor_sync(0xffffffffu, v01, mask);
                v10 += __shfl_xor_sync(0xffffffffu, v10, mask);
                v11 += __shfl_xor_sync(0xffffffffu, v11, mask);
            }
            if (lane < 4) {
                const size_t o0 = (size_t)blockIdx.y*16 + wm*8 + 2*mt;
                float2 s0; s0.x = v00; s0.y = v01;
                float2 s1; s1.x = v10; s1.y = v11;
                *(float2*)&S[o0*D1_ + c]     = s0;
                *(float2*)&S[(o0+1)*D1_ + c] = s1;
            }
        }
    }
}

// ---------------------------------------------------------------------------
// pp[n] = ((S[oct h] + S[oct h+1]) / 16) @ W2 + b2   (patch = two octets)
// ---------------------------------------------------------------------------
__global__ void __launch_bounds__(256)
pp_kernel(const float* __restrict__ S, const float* __restrict__ W2,
          const float* __restrict__ b2, float* __restrict__ pp)
{
    __shared__ float sP[8][D1_];
    const int tid = threadIdx.x;

#pragma unroll
    for (int rr = 0; rr < 8; rr++) {
        const int n = blockIdx.x*8 + rr;
        const int b = n / H_, h = n % H_;
        const float* s0 = S + ((size_t)b*512 + h)*D1_;
        sP[rr][tid] = (s0[tid] + s0[D1_ + tid]) * (1.f/16.f);
    }
    __syncthreads();

    const int i = tid & 63;
#pragma unroll
    for (int rr = tid >> 6; rr < 8; rr += 4) {
        float acc = b2[i];
#pragma unroll
        for (int j = 0; j < D1_; j++) acc += sP[rr][j] * W2[j*DF_ + i];
        pp[(blockIdx.x*8 + rr)*DF_ + i] = acc;
    }
}

// ---------------------------------------------------------------------------
// Fused per-row attention, 4 rows per 256-thread block (branchless top-8).
// ---------------------------------------------------------------------------
__global__ void __launch_bounds__(256)
attn_kernel(const float* __restrict__ pp,
            const float* __restrict__ Wq, const float* __restrict__ Wk,
            const float* __restrict__ Wv,
            const float* __restrict__ Wagg, const float* __restrict__ bagg,
            float* __restrict__ z)
{
    const int r = threadIdx.x >> 6;
    const int i = threadIdx.x & 63;
    const int n = blockIdx.x*4 + r;

    __shared__ float sp[4][DF_], sq[4][DF_], sk[4][DF_], sv[4][DF_], sAv[4][DF_];

    sp[r][i] = pp[n*DF_ + i];
    __syncthreads();

    float q = 0.f, k = 0.f, v = 0.f;
#pragma unroll
    for (int j = 0; j < DF_; j++) {
        const float x = sp[r][j];
        q += x * Wq[j*DF_ + i];
        k += x * Wk[j*DF_ + i];
        v += x * Wv[j*DF_ + i];
    }
    sq[r][i] = q; sk[r][i] = k; sv[r][i] = v;
    __syncthreads();

    float nq = 0.f, nk = 0.f;
#pragma unroll
    for (int j = 0; j < DF_; j++) { nq += sq[r][j]*sq[r][j]; nk += sk[r][j]*sk[r][j]; }
    const float inv_nq = 1.f / (sqrtf(nq) + EPS_);
    const float inv_nk = 1.f / (sqrtf(nk) + EPS_);

    const float c1 = (sq[r][i]*inv_nq) * inv_nk;
    const float c2 = (sk[r][i]*inv_nk) * inv_nq;

    uint32_t h[8];
#pragma unroll
    for (int t = 0; t < 8; t++) h[t] = 0u;

#pragma unroll
    for (int j = 0; j < DF_; j++) {
        const float s = c1*sk[r][j] - c2*sq[r][j];
        uint32_t u = __float_as_uint(s);
        u = ((int32_t)u < 0) ? ~u : (u | 0x80000000u);
        u = (u & 0xFFFFFFC0u) | (uint32_t)(63 - j);
        h[0] = (h[0] > u) ? h[0] : u;
#pragma unroll
        for (int t = 0; t < 7; t++) {
            const uint32_t lo = (h[t] < h[t+1]) ? h[t] : h[t+1];
            const uint32_t hi = (h[t] < h[t+1]) ? h[t+1] : h[t];
            h[t] = lo; h[t+1] = hi;
        }
    }

    float sum8 = 0.f, av = 0.f;
#pragma unroll
    for (int t = 0; t < 8; t++) {
        const int j = 63 - (int)(h[t] & 63u);
        const float s = c1*sk[r][j] - c2*sq[r][j];
        if (s > 0.f) {
            const float e = __expf(2.f*s);
            const float a = 1.f - __fdividef(2.f, e + 1.f);
            sum8 += a;
            av   += a * sv[r][j];
        }
    }
    av *= 1.f / fmaxf(sum8, EPS_);

    sAv[r][i] = av;
    __syncthreads();

    float acc = bagg[i];
#pragma unroll
    for (int j = 0; j < DF_; j++) acc += sAv[r][j]*Wagg[j*DF_ + i];
    z[n*DF_ + i] = (acc > 0.f) ? acc : 0.01f*acc;
}

// ---------------------------------------------------------------------------
// Fused decode + overlap: out rows within octet o are identical:
//   out[b, 8o+r, :] = za[b,o] @ Wdec + bdec,
//   za[b,o] = (z[b,o-1]+z[b,o])/2   (o in 1..510),  z[b,0] / z[b,510] at edges.
// Block = 16 octets of one batch. Result broadcast-stored to 8 l-rows each.
// ---------------------------------------------------------------------------
__global__ void __launch_bounds__(256)
zdec_out_kernel(const float* __restrict__ z, const float* __restrict__ Wdec,
                const float* __restrict__ bdec, float* __restrict__ out)
{
    __shared__ float za[16*DF_];
    __shared__ float ws[DF_*132];
    const int tid = threadIdx.x;
    const int b   = blockIdx.x >> 5;          // 32 blocks per batch
    const int o0  = (blockIdx.x & 31) * 16;   // starting octet in batch

    // Build za: 16 rows x 64, one float4 per thread (256 threads x 4 = 1024)
    {
        const int row = tid >> 4;             // 0..15
        const int c4  = (tid & 15) * 4;       // 0..60
        const int o   = o0 + row;
        const int hA  = (o == 0)   ? 0   : o - 1;
        const int hB  = (o == 511) ? 510 : o;
        const float w = (hA == hB) ? 1.f : 0.5f;
        const float* zA = &z[((size_t)b*H_ + hA)*DF_ + c4];
        const float* zB = &z[((size_t)b*H_ + hB)*DF_ + c4];
        const float4 a = *(const float4*)zA;
        const float4 bb = *(const float4*)zB;
        float4 o4;
        o4.x = (a.x + bb.x)*w; o4.y = (a.y + bb.y)*w;
        o4.z = (a.z + bb.z)*w; o4.w = (a.w + bb.w)*w;
        if (hA == hB) { o4.x = a.x; o4.y = a.y; o4.z = a.z; o4.w = a.w; }
        *(float4*)&za[row*DF_ + c4] = o4;
    }

    const int ct64 = tid & 63;                // column pair index
    const int rt   = tid >> 6;                // row-group (4 rows each)

    for (int ct = 0; ct < 4; ct++) {          // 4 chunks of 128 cols
        __syncthreads();
#pragma unroll
        for (int i = 0; i < 8; i++) {
            const int idx = tid + i*256;
            const int r = idx >> 5, c4 = (idx & 31)*4;
            *(float4*)&ws[r*132 + c4] = *(const float4*)&Wdec[(size_t)r*D_ + ct*128 + c4];
        }
        __syncthreads();

        const int c = ct*128 + ct64*2;
        const float bd0 = bdec[c], bd1 = bdec[c+1];

        float acc[4][2];
#pragma unroll
        for (int r=0;r<4;r++) { acc[r][0]=0.f; acc[r][1]=0.f; }
#pragma unroll
        for (int k = 0; k < DF_; k++) {
            const float2 w = *(const float2*)&ws[k*132 + ct64*2];
#pragma unroll
            for (int r = 0; r < 4; r++) {
                const float zv = za[(rt*4+r)*DF_ + k];
                acc[r][0] += zv*w.x;
                acc[r][1] += zv*w.y;
            }
        }
#pragma unroll
        for (int r = 0; r < 4; r++) {
            float2 o2; o2.x = acc[r][0] + bd0; o2.y = acc[r][1] + bd1;
            const int o = o0 + rt*4 + r;
            float* orow = &out[((size_t)b*L_ + 8*o)*D_ + c];
#pragma unroll
            for (int rep = 0; rep < 8; rep++)
                *(float2*)&orow[(size_t)rep*D_] = o2;
        }
    }
}

// ---------------------------------------------------------------------------
extern "C" void kernel_launch(void* const* d_in, const int* in_sizes, int n_in,
                              void* d_out, int out_size)
{
    const float* X    = (const float*)d_in[0];
    const float* W1   = (const float*)d_in[1];
    const float* b1   = (const float*)d_in[2];
    const float* W2   = (const float*)d_in[3];
    const float* b2   = (const float*)d_in[4];
    const float* Wq   = (const float*)d_in[5];
    const float* Wk   = (const float*)d_in[6];
    const float* Wv   = (const float*)d_in[7];
    const float* Wagg = (const float*)d_in[8];
    const float* bagg = (const float*)d_in[9];
    const float* Wdec = (const float*)d_in[10];
    const float* bdec = (const float*)d_in[11];
    float* out = (float*)d_out;

    float *S, *pp, *z;
    cudaGetSymbolAddress((void**)&S,  g_S);
    cudaGetSymbolAddress((void**)&pp, g_pp);
    cudaGetSymbolAddress((void**)&z,  g_z);

    cudaFuncSetAttribute(gemm_h,
        cudaFuncAttributeMaxDynamicSharedMemorySize, GEMM_SMEM);

    // 1) S = octet-sums of leaky(X @ W1 + b1)   (fp16-split MMA, ldmatrix)
    gemm_h<<<dim3(D1_/128, M_/128), 256, GEMM_SMEM>>>(X, W1, b1, S, M_, D_, D1_);

    // 2) pp = ((S[h] + S[h+1]) / 16) @ W2 + b2
    pp_kernel<<<NROWS/8, 256>>>(S, W2, b2, pp);

    // 3) fused qkv + attention + top-8 + aggregate
    attn_kernel<<<NROWS/4, 256>>>(pp, Wq, Wk, Wv, Wagg, bagg, z);

    // 4) out = broadcast( za @ Wdec + bdec )   (fused decode+overlap)
    zdec_out_kernel<<<NOCT/16, 256>>>(z, Wdec, bdec, out);
}